// round 14
// baseline (speedup 1.0000x reference)
#include <cuda_runtime.h>

#define HEADS   8
#define NTOK    4096
#define RANK    820        /* # elements strictly below threshold */
#define ROWS    4
#define THREADS 256
#define CAPR    384        /* max candidates for register bisect */
#define NREG    12         /* CAPR/32 */

// ---------------- device scratch ----------------
__device__ float  g_qraw[32 * NTOK];      // [head*4+c][n]
__device__ float4 g_kT  [HEADS * NTOK];   // [head][n] -> (c0,c1,c2,c3)
__device__ float4 g_vT  [HEADS * NTOK];
__device__ float  g_qs[32];
__device__ float  g_ks[32];
__device__ float  g_kmean[HEADS * 4];
__device__ float  g_km2[HEADS * 16];
__device__ float  g_pre[128 * 1024];      // attention output in proj layout [ch][pixel]

// dummy kernel: keeps ncu's fixed capture slot on attn_kernel
__global__ void marker_kernel() {}

// ---------------- kernel 1: qkv = 1x1x1 group conv + depthwise 3x3 ----------------
__global__ void prep_kernel(const float* __restrict__ x,
                            const float* __restrict__ wqkv,
                            const float* __restrict__ wdw) {
    __shared__ float sh[34][34];
    int o  = blockIdx.x;
    int cd = blockIdx.y;
    int tid = threadIdx.x;
    for (int i = tid; i < 34 * 34; i += THREADS) ((float*)sh)[i] = 0.f;
    __syncthreads();
    float w0 = wqkv[o * 4 + 0], w1 = wqkv[o * 4 + 1];
    float w2 = wqkv[o * 4 + 2], w3 = wqkv[o * 4 + 3];
    for (int p = tid; p < 1024; p += THREADS) {
        int y = p >> 5, xx = p & 31;
        float v = w0 * x[(0 * 32 + cd) * 1024 + p]
                + w1 * x[(1 * 32 + cd) * 1024 + p]
                + w2 * x[(2 * 32 + cd) * 1024 + p]
                + w3 * x[(3 * 32 + cd) * 1024 + p];
        sh[y + 1][xx + 1] = v;
    }
    __syncthreads();
    float k00 = wdw[o*9+0], k01 = wdw[o*9+1], k02 = wdw[o*9+2];
    float k10 = wdw[o*9+3], k11 = wdw[o*9+4], k12 = wdw[o*9+5];
    float k20 = wdw[o*9+6], k21 = wdw[o*9+7], k22 = wdw[o*9+8];
    int g = o >> 2, tt = o & 3;
    int head = cd >> 2, c = cd & 3;
    for (int p = tid; p < 1024; p += THREADS) {
        int y = p >> 5, xx = p & 31;
        float s = k00*sh[y  ][xx] + k01*sh[y  ][xx+1] + k02*sh[y  ][xx+2]
                + k10*sh[y+1][xx] + k11*sh[y+1][xx+1] + k12*sh[y+1][xx+2]
                + k20*sh[y+2][xx] + k21*sh[y+2][xx+1] + k22*sh[y+2][xx+2];
        int n = (p << 2) + tt;
        if (g == 0)      g_qraw[cd * NTOK + n] = s;
        else if (g == 1) ((float*)g_kT)[(head * NTOK + n) * 4 + c] = s;
        else             ((float*)g_vT)[(head * NTOK + n) * 4 + c] = s;
    }
}

// ---------------- kernel 2: norms + per-head k stats ----------------
__constant__ int c_pa[10] = {0,0,0,0,1,1,1,2,2,3};
__constant__ int c_pb[10] = {0,1,2,3,1,2,3,2,3,3};

__global__ void norm_kernel() {
    int i = blockIdx.x;
    int tid = threadIdx.x;
    int lane = tid & 31, wid = tid >> 5;
    __shared__ float red[8 * 14];

    if (i < 64) {
        float s = 0.f;
        if (i < 32) {
            const float* q = g_qraw + i * NTOK;
            for (int n = tid; n < NTOK; n += THREADS) { float v = q[n]; s += v * v; }
        } else {
            int j = i - 32; int head = j >> 2, c = j & 3;
            const float* k = ((const float*)g_kT) + head * NTOK * 4 + c;
            for (int n = tid; n < NTOK; n += THREADS) { float v = k[n * 4]; s += v * v; }
        }
        for (int off = 16; off; off >>= 1) s += __shfl_down_sync(0xffffffffu, s, off);
        if (lane == 0) red[wid] = s;
        __syncthreads();
        if (tid == 0) {
            float t = 0.f;
            for (int w = 0; w < 8; w++) t += red[w];
            float scale = 1.f / fmaxf(sqrtf(t), 1e-12f);
            if (i < 32) g_qs[i] = scale; else g_ks[i - 32] = scale;
        }
    } else {
        int head = i - 64;
        const float4* kt = g_kT + head * NTOK;
        float vals[14];
        #pragma unroll
        for (int q = 0; q < 14; q++) vals[q] = 0.f;
        for (int n = tid; n < NTOK; n += THREADS) {
            float4 k = kt[n];
            vals[0] += k.x; vals[1] += k.y; vals[2] += k.z; vals[3] += k.w;
            vals[4]  += k.x*k.x; vals[5]  += k.x*k.y; vals[6]  += k.x*k.z; vals[7] += k.x*k.w;
            vals[8]  += k.y*k.y; vals[9]  += k.y*k.z; vals[10] += k.y*k.w;
            vals[11] += k.z*k.z; vals[12] += k.z*k.w; vals[13] += k.w*k.w;
        }
        #pragma unroll
        for (int q = 0; q < 14; q++)
            for (int off = 16; off; off >>= 1)
                vals[q] += __shfl_down_sync(0xffffffffu, vals[q], off);
        if (lane == 0) {
            #pragma unroll
            for (int q = 0; q < 14; q++) red[wid * 14 + q] = vals[q];
        }
        __syncthreads();
        if (tid < 14) {
            float s = 0.f;
            for (int w = 0; w < 8; w++) s += red[w * 14 + tid];
            s *= (1.f / 4096.f);
            if (tid < 4) g_kmean[head * 4 + tid] = s;
            else {
                int a = c_pa[tid - 4], b = c_pb[tid - 4];
                g_km2[head * 16 + a * 4 + b] = s;
                g_km2[head * 16 + b * 4 + a] = s;
            }
        }
    }
}

// ---------------- kernel 3: SINGLE fused pass + candidate fix-up ----------------
__device__ __forceinline__ unsigned ordkey(float f) {
    unsigned u = __float_as_uint(f);
    return u ^ (0x80000000u | (unsigned)((int)u >> 31));
}
__device__ __forceinline__ float inv_ordkey(unsigned u) {
    return __uint_as_float(u ^ (0x80000000u | ~(unsigned)((int)u >> 31)));
}
__device__ __forceinline__ unsigned next_pivot(unsigned lo, unsigned hi, int clo, int chi, int useInterp) {
    unsigned span = hi - lo;
    unsigned step;
    if (!useInterp) step = span >> 1;
    else {
        float fr = (float)(RANK + 1 - clo) / (float)(chi - clo);
        step = (unsigned)(fr * (float)span);
        unsigned mn = span >> 4; if (!mn) mn = 1;
        if (step < mn) step = mn;
        if (step > span - mn) step = span - mn;
    }
    if (!step) step = 1;
    return lo + step;
}
// degree-7 Taylor exp: fp32-exact for the tiny |s| here
__device__ __forceinline__ float exp_poly(float s) {
    float p = fmaf(s, 1.f/5040.f, 1.f/720.f);
    p = fmaf(p, s, 1.f/120.f);
    p = fmaf(p, s, 1.f/24.f);
    p = fmaf(p, s, 1.f/6.f);
    p = fmaf(p, s, 0.5f);
    p = fmaf(p, s, 1.f);
    p = fmaf(p, s, 1.f);
    return p;
}

#define SCORE(cfr, kk) fmaf((cfr).x,(kk).x, fmaf((cfr).y,(kk).y, fmaf((cfr).z,(kk).z, (cfr).w*(kk).w)))

__global__ void __launch_bounds__(THREADS, 2) attn_kernel(const float* __restrict__ temperature) {
    __shared__ unsigned       keys[ROWS * CAPR];
    __shared__ unsigned short idxb[ROWS * CAPR];
    __shared__ unsigned cnt[4];
    __shared__ unsigned state[4];        // 0=bisect 1=buffer-search 2=done 3=compact-pending
    __shared__ unsigned fastf[4];        // 1 = fast-path accumulation valid
    __shared__ unsigned slo[4], shi[4];
    __shared__ int      sclo[4], schi[4];
    __shared__ unsigned spiv[4], stkey[4], stgt[4];
    __shared__ float    sMb[4];
    __shared__ int      sany[1];
    __shared__ unsigned wred[32];
    __shared__ float    sred[160];
    __shared__ float    sfin[20];

    int bx   = blockIdx.x;
    int head = bx >> 10;
    int n0   = (bx & 1023) << 2;
    int tid  = threadIdx.x;
    int lane = tid & 31, wid = tid >> 5;

    float temp = temperature[head];
    float4 cf[ROWS];
    #pragma unroll
    for (int r = 0; r < ROWS; r++) {
        int n = n0 + r;
        float a0 = g_qraw[(head*4+0)*NTOK + n] * g_qs[head*4+0] * g_ks[head*4+0] * temp;
        float a1 = g_qraw[(head*4+1)*NTOK + n] * g_qs[head*4+1] * g_ks[head*4+1] * temp;
        float a2 = g_qraw[(head*4+2)*NTOK + n] * g_qs[head*4+2] * g_ks[head*4+2] * temp;
        float a3 = g_qraw[(head*4+3)*NTOK + n] * g_qs[head*4+3] * g_ks[head*4+3] * temp;
        cf[r] = make_float4(a0, a1, a2, a3);
    }

    // ---- analytic per-row pivots (quantiles ~0.165 / ~0.235) ----
    float p1f[ROWS], p5f[ROWS];
    {
        float mu0 = g_kmean[head*4+0], mu1 = g_kmean[head*4+1];
        float mu2 = g_kmean[head*4+2], mu3 = g_kmean[head*4+3];
        const float* M = g_km2 + head * 16;
        float m00=M[0], m01=M[1], m02=M[2], m03=M[3];
        float m11=M[5], m12=M[6], m13=M[7];
        float m22=M[10], m23=M[11], m33=M[15];
        #pragma unroll
        for (int r = 0; r < ROWS; r++) {
            float cx = cf[r].x, cy = cf[r].y, cz = cf[r].z, cw = cf[r].w;
            float mean = cx*mu0 + cy*mu1 + cz*mu2 + cw*mu3;
            float t0 = m00*cx + m01*cy + m02*cz + m03*cw;
            float t1 = m01*cx + m11*cy + m12*cz + m13*cw;
            float t2 = m02*cx + m12*cy + m22*cz + m23*cw;
            float t3 = m03*cx + m13*cy + m23*cz + m33*cw;
            float es2 = cx*t0 + cy*t1 + cz*t2 + cw*t3;
            float var = es2 - mean * mean;
            float sig = sqrtf(fmaxf(var, 0.f));
            p1f[r] = fmaf(-0.9741f, sig, mean);
            p5f[r] = fmaf(-0.7225f, sig, mean);
        }
    }
    if (tid == 0) {
        #pragma unroll
        for (int r = 0; r < ROWS; r++) {
            sMb[r] = fabsf(cf[r].x) + fabsf(cf[r].y) + fabsf(cf[r].z) + fabsf(cf[r].w);
            cnt[r] = 0;
        }
    }
    __syncthreads();

    // ---- single fused pass: stream k AND v once ----
    //   - count below p1
    //   - compact window [p1,p5) candidates (key + token index)
    //   - accumulate exp(s)*v for s >= p5 (speculative upper part of kept set)
    float zz[ROWS] = {0.f, 0.f, 0.f, 0.f};
    float4 acc[ROWS];
    #pragma unroll
    for (int r = 0; r < ROWS; r++) acc[r] = make_float4(0.f, 0.f, 0.f, 0.f);
    int c1t[ROWS] = {0,0,0,0};
    const float4* kt = g_kT + head * NTOK;
    const float4* vt = g_vT + head * NTOK;
    #pragma unroll
    for (int jo = 0; jo < 4; jo++) {
        int mb = (jo << 10) + (tid << 2);
        float4 k0 = __ldg(&kt[mb+0]);
        float4 k1 = __ldg(&kt[mb+1]);
        float4 k2 = __ldg(&kt[mb+2]);
        float4 k3 = __ldg(&kt[mb+3]);
        float4 v0 = __ldg(&vt[mb+0]);
        float4 v1 = __ldg(&vt[mb+1]);
        float4 v2 = __ldg(&vt[mb+2]);
        float4 v3 = __ldg(&vt[mb+3]);
        #pragma unroll
        for (int r = 0; r < ROWS; r++) {
            float s0 = SCORE(cf[r], k0);
            float s1 = SCORE(cf[r], k1);
            float s2 = SCORE(cf[r], k2);
            float s3 = SCORE(cf[r], k3);
            float p1 = p1f[r], p5 = p5f[r];
            int b0 = (s0 < p1), b1 = (s1 < p1), b2 = (s2 < p1), b3 = (s3 < p1);
            c1t[r] += b0 + b1 + b2 + b3;
            // speculative accumulation for s >= p5
            float w0 = (s0 >= p5) ? exp_poly(s0) : 0.f;
            float w1 = (s1 >= p5) ? exp_poly(s1) : 0.f;
            float w2 = (s2 >= p5) ? exp_poly(s2) : 0.f;
            float w3 = (s3 >= p5) ? exp_poly(s3) : 0.f;
            zz[r] += (w0 + w1) + (w2 + w3);
            acc[r].x += w0*v0.x + w1*v1.x + w2*v2.x + w3*v3.x;
            acc[r].y += w0*v0.y + w1*v1.y + w2*v2.y + w3*v3.y;
            acc[r].z += w0*v0.z + w1*v1.z + w2*v2.z + w3*v3.z;
            acc[r].w += w0*v0.w + w1*v1.w + w2*v2.w + w3*v3.w;
            // window compaction
            int wx = (!b0) & (s0 < p5);
            int wy = (!b1) & (s1 < p5);
            int wz = (!b2) & (s2 < p5);
            int ww = (!b3) & (s3 < p5);
            int nc = wx + wy + wz + ww;
            if (nc) {
                unsigned bs = atomicAdd(&cnt[r], (unsigned)nc);
                if (bs + (unsigned)nc <= CAPR) {
                    unsigned p = bs;
                    if (wx) { keys[r*CAPR + p] = ordkey(s0); idxb[r*CAPR + p] = (unsigned short)(mb+0); p++; }
                    if (wy) { keys[r*CAPR + p] = ordkey(s1); idxb[r*CAPR + p] = (unsigned short)(mb+1); p++; }
                    if (wz) { keys[r*CAPR + p] = ordkey(s2); idxb[r*CAPR + p] = (unsigned short)(mb+2); p++; }
                    if (ww) { keys[r*CAPR + p] = ordkey(s3); idxb[r*CAPR + p] = (unsigned short)(mb+3); p++; }
                }
            }
        }
    }
    #pragma unroll
    for (int r = 0; r < ROWS; r++) c1t[r] = __reduce_add_sync(0xffffffffu, c1t[r]);
    if (lane == 0) {
        #pragma unroll
        for (int r = 0; r < ROWS; r++) wred[wid*4 + r] = (unsigned)c1t[r];
    }
    __syncthreads();

    // ---- classify rows ----
    if (tid < 4) {
        int c1v = 0;
        for (int w = 0; w < 8; w++) c1v += (int)wred[w*4 + tid];
        int cw  = (int)cnt[tid];
        int c5v = c1v + cw;
        unsigned p1 = ordkey(p1f[tid]), p5 = ordkey(p5f[tid]);
        if (c1v <= RANK && RANK < c5v && cw <= CAPR) {
            state[tid] = 1u; fastf[tid] = 1u;
            slo[tid] = p1; shi[tid] = p5; stgt[tid] = (unsigned)(RANK - c1v);
        } else {
            fastf[tid] = 0u;
            unsigned lo, hi; int clo, chi;
            if (RANK < c1v)      { lo = 0u; hi = p1; clo = 0;   chi = c1v; }
            else if (RANK < c5v) { lo = p1; hi = p5; clo = c1v; chi = c5v; }
            else                 { lo = p5; hi = ordkey(sMb[tid]) + 1u; clo = c5v; chi = NTOK; }
            slo[tid] = lo; shi[tid] = hi; sclo[tid] = clo; schi[tid] = chi;
            if (hi - lo <= 1u)          { stkey[tid] = lo; state[tid] = 2u; }
            else if (chi - clo <= CAPR) { state[tid] = 3u; }
            else { state[tid] = 0u; spiv[tid] = next_pivot(lo, hi, clo, chi, 1); }
        }
    }

    // ---- fallback bisect loop (rare): recompute scores from k ----
    for (int iter = 0; iter < 72; iter++) {
        __syncthreads();
        if (tid == 0)
            sany[0] = (state[0]==0) | (state[1]==0) | (state[2]==0) | (state[3]==0);
        __syncthreads();
        if (!sany[0]) break;
        float pvf[ROWS]; int act[ROWS];
        #pragma unroll
        for (int r = 0; r < ROWS; r++) { act[r] = (state[r] == 0); pvf[r] = inv_ordkey(spiv[r]); }
        int cr[ROWS] = {0,0,0,0};
        #pragma unroll 1
        for (int jo = 0; jo < 4; jo++) {
            int mb = (jo << 10) + (tid << 2);
            float4 k0 = __ldg(&kt[mb+0]);
            float4 k1 = __ldg(&kt[mb+1]);
            float4 k2 = __ldg(&kt[mb+2]);
            float4 k3 = __ldg(&kt[mb+3]);
            #pragma unroll
            for (int r = 0; r < ROWS; r++) {
                if (act[r]) {
                    float s0 = SCORE(cf[r], k0);
                    float s1 = SCORE(cf[r], k1);
                    float s2 = SCORE(cf[r], k2);
                    float s3 = SCORE(cf[r], k3);
                    cr[r] += (s0 < pvf[r]) + (s1 < pvf[r]) + (s2 < pvf[r]) + (s3 < pvf[r]);
                }
            }
        }
        #pragma unroll
        for (int r = 0; r < ROWS; r++) cr[r] = __reduce_add_sync(0xffffffffu, cr[r]);
        if (lane == 0) {
            #pragma unroll
            for (int r = 0; r < ROWS; r++) wred[wid*4 + r] = (unsigned)cr[r];
        }
        __syncthreads();
        if (tid < 4 && state[tid] == 0) {
            int tot = 0;
            for (int w = 0; w < 8; w++) tot += (int)wred[w*4 + tid];
            if (tot <= RANK) { slo[tid] = spiv[tid]; sclo[tid] = tot; }
            else             { shi[tid] = spiv[tid]; schi[tid] = tot; }
            unsigned lo = slo[tid], hi = shi[tid];
            int cc = schi[tid] - sclo[tid];
            if (hi - lo <= 1u)      { stkey[tid] = lo; state[tid] = 2; }
            else if (cc <= CAPR)    { state[tid] = 3; }
            else spiv[tid] = next_pivot(lo, hi, sclo[tid], schi[tid], !(iter & 1));
        }
    }
    __syncthreads();
    if (tid < 4) {
        if (state[tid] == 0) { stkey[tid] = slo[tid]; state[tid] = 2; } // safety
        if (state[tid] == 3) cnt[tid] = 0;
    }
    __syncthreads();

    // ---- fallback compaction (rare): keys only, recompute from k ----
    {
        bool anyc = (state[0]==3) | (state[1]==3) | (state[2]==3) | (state[3]==3);
        if (anyc) {
            #pragma unroll 1
            for (int r = 0; r < ROWS; r++) {
                if (state[r] == 3) {
                    float lof = inv_ordkey(slo[r]);
                    float hif = inv_ordkey(shi[r]);
                    #pragma unroll 1
                    for (int jo = 0; jo < 4; jo++) {
                        int mb = (jo << 10) + (tid << 2);
                        float4 k0 = __ldg(&kt[mb+0]);
                        float4 k1 = __ldg(&kt[mb+1]);
                        float4 k2 = __ldg(&kt[mb+2]);
                        float4 k3 = __ldg(&kt[mb+3]);
                        float s0 = SCORE(cf[r], k0);
                        float s1 = SCORE(cf[r], k1);
                        float s2 = SCORE(cf[r], k2);
                        float s3 = SCORE(cf[r], k3);
                        int wx = (s0 >= lof) & (s0 < hif);
                        int wy = (s1 >= lof) & (s1 < hif);
                        int wz = (s2 >= lof) & (s2 < hif);
                        int ww = (s3 >= lof) & (s3 < hif);
                        int nc = wx + wy + wz + ww;
                        if (nc) {
                            unsigned bs = atomicAdd(&cnt[r], (unsigned)nc);
                            if (bs + (unsigned)nc <= CAPR) {
                                unsigned p = bs;
                                if (wx) keys[r*CAPR + p++] = ordkey(s0);
                                if (wy) keys[r*CAPR + p++] = ordkey(s1);
                                if (wz) keys[r*CAPR + p++] = ordkey(s2);
                                if (ww) keys[r*CAPR + p++] = ordkey(s3);
                            }
                        }
                    }
                }
            }
            __syncthreads();
            if (tid < 4 && state[tid] == 3) {
                stgt[tid] = (unsigned)(RANK - sclo[tid]);
                state[tid] = 1;
            }
            __syncthreads();
        }
    }

    // ---- warp-register bisect over candidate keys (1 warp / row) ----
    if (wid < 4 && state[wid] == 1) {
        int c = (int)cnt[wid]; if (c > CAPR) c = CAPR;
        unsigned cand[NREG];
        #pragma unroll
        for (int i = 0; i < NREG; i++) {
            int idx = i * 32 + lane;
            cand[i] = (idx < c) ? keys[wid*CAPR + idx] : 0xFFFFFFFFu;
        }
        unsigned lo = slo[wid], hi = shi[wid], tgt = stgt[wid];
        while (hi - lo > 1u) {
            unsigned mid = lo + ((hi - lo) >> 1);
            unsigned cb = 0;
            #pragma unroll
            for (int i = 0; i < NREG; i++) cb += (cand[i] < mid);
            cb = __reduce_add_sync(0xffffffffu, cb);
            if (cb <= tgt) lo = mid; else hi = mid;
        }
        if (lane == 0) stkey[wid] = lo;
    }
    __syncthreads();

    // ---- fast rows: add kept window candidates (gather v by index) ----
    if (wid < 4 && fastf[wid]) {
        int r = wid;
        unsigned tk = stkey[r];
        int c = (int)cnt[r]; if (c > CAPR) c = CAPR;
        for (int i = lane; i < c; i += 32) {
            unsigned u = keys[r*CAPR + i];
            if (u >= tk) {
                float4 v = __ldg(&vt[idxb[r*CAPR + i]]);
                float w = exp_poly(inv_ordkey(u));
                zz[r] += w;
                acc[r].x += w*v.x; acc[r].y += w*v.y;
                acc[r].z += w*v.z; acc[r].w += w*v.w;
            }
        }
    }

    // ---- slow rows (rare): discard speculative sums, full masked re-accumulation ----
    {
        int slow = (!fastf[0]) | ((!fastf[1]) << 1) | ((!fastf[2]) << 2) | ((!fastf[3]) << 3);
        if (slow) {
            float thrf[ROWS]; int act[ROWS];
            #pragma unroll
            for (int r = 0; r < ROWS; r++) {
                act[r] = (slow >> r) & 1;
                thrf[r] = inv_ordkey(stkey[r]);
                if (act[r]) { zz[r] = 0.f; acc[r] = make_float4(0.f, 0.f, 0.f, 0.f); }
            }
            #pragma unroll 1
            for (int jo = 0; jo < 4; jo++) {
                int mb = (jo << 10) + (tid << 2);
                float4 k0 = __ldg(&kt[mb+0]);
                float4 k1 = __ldg(&kt[mb+1]);
                float4 k2 = __ldg(&kt[mb+2]);
                float4 k3 = __ldg(&kt[mb+3]);
                float4 v0 = __ldg(&vt[mb+0]);
                float4 v1 = __ldg(&vt[mb+1]);
                float4 v2 = __ldg(&vt[mb+2]);
                float4 v3 = __ldg(&vt[mb+3]);
                #pragma unroll
                for (int r = 0; r < ROWS; r++) {
                    if (act[r]) {
                        float s0 = SCORE(cf[r], k0);
                        float s1 = SCORE(cf[r], k1);
                        float s2 = SCORE(cf[r], k2);
                        float s3 = SCORE(cf[r], k3);
                        float w0 = (s0 >= thrf[r]) ? exp_poly(s0) : 0.f;
                        float w1 = (s1 >= thrf[r]) ? exp_poly(s1) : 0.f;
                        float w2 = (s2 >= thrf[r]) ? exp_poly(s2) : 0.f;
                        float w3 = (s3 >= thrf[r]) ? exp_poly(s3) : 0.f;
                        zz[r] += (w0 + w1) + (w2 + w3);
                        acc[r].x += w0*v0.x + w1*v1.x + w2*v2.x + w3*v3.x;
                        acc[r].y += w0*v0.y + w1*v1.y + w2*v2.y + w3*v3.y;
                        acc[r].z += w0*v0.z + w1*v1.z + w2*v2.z + w3*v3.z;
                        acc[r].w += w0*v0.w + w1*v1.w + w2*v2.w + w3*v3.w;
                    }
                }
            }
        }
    }

    // ---- block-reduce 20 accumulators ----
    float vals[20];
    #pragma unroll
    for (int r = 0; r < ROWS; r++) {
        vals[r*5 + 0] = zz[r];
        vals[r*5 + 1] = acc[r].x; vals[r*5 + 2] = acc[r].y;
        vals[r*5 + 3] = acc[r].z; vals[r*5 + 4] = acc[r].w;
    }
    #pragma unroll
    for (int q = 0; q < 20; q++)
        for (int off = 16; off; off >>= 1)
            vals[q] += __shfl_down_sync(0xffffffffu, vals[q], off);
    if (lane == 0) {
        #pragma unroll
        for (int q = 0; q < 20; q++) sred[q*8 + wid] = vals[q];
    }
    __syncthreads();
    if (tid < 20) {
        float s = 0.f;
        for (int w = 0; w < 8; w++) s += sred[tid*8 + w];
        sfin[tid] = s;
    }
    __syncthreads();
    if (tid < 16) {
        int r = tid >> 2, c = tid & 3;
        float val = sfin[r*5 + 1 + c] / sfin[r*5 + 0];
        int n = n0 + r;
        int tt = n & 3, pixel = n >> 2;
        int ch = tt * 32 + head * 4 + c;
        g_pre[ch * 1024 + pixel] = val;
    }
}

// ---------------- kernel 4: final 1x1 projection ----------------
__global__ void proj_kernel(const float* __restrict__ wproj, float* __restrict__ out) {
    int idx = blockIdx.x * THREADS + threadIdx.x;
    int o = idx >> 10, p = idx & 1023;
    const float* w = wproj + o * 128;
    float s = 0.f;
    #pragma unroll 8
    for (int ch = 0; ch < 128; ch++) s += w[ch] * g_pre[ch * 1024 + p];
    out[idx] = s;
}

// ---------------- launch ----------------
extern "C" void kernel_launch(void* const* d_in, const int* in_sizes, int n_in,
                              void* d_out, int out_size) {
    (void)in_sizes; (void)n_in; (void)out_size;
    const float* x           = (const float*)d_in[0];
    const float* temperature = (const float*)d_in[1];
    const float* wqkv        = (const float*)d_in[2];
    const float* wdw         = (const float*)d_in[3];
    const float* wproj       = (const float*)d_in[4];
    float* out = (float*)d_out;

    marker_kernel<<<1, 32>>>();   // keeps ncu capture slot on attn
    prep_kernel<<<dim3(12, 32), THREADS>>>(x, wqkv, wdw);
    norm_kernel<<<72, THREADS>>>();
    attn_kernel<<<HEADS * (NTOK / ROWS), THREADS>>>(temperature);
    proj_kernel<<<(128 * 1024) / THREADS, THREADS>>>(wproj, out);
}

// round 15
// speedup vs baseline: 1.2027x; 1.2027x over previous
#include <cuda_runtime.h>

#define HEADS   8
#define NTOK    4096
#define RANK    820        /* # elements strictly below threshold */
#define ROWS    4
#define THREADS 256
#define CAPR    384        /* max candidates for register bisect */
#define NREG    12         /* CAPR/32 */
#define SEG     72         /* per-(row,warp) segment capacity */

// ---------------- device scratch ----------------
__device__ float  g_qraw[32 * NTOK];      // [head*4+c][n]
__device__ float4 g_kT  [HEADS * NTOK];   // [head][n] -> (c0,c1,c2,c3)
__device__ float4 g_vT  [HEADS * NTOK];
__device__ float  g_qs[32];
__device__ float  g_ks[32];
__device__ float  g_kmean[HEADS * 4];
__device__ float  g_km2[HEADS * 16];
__device__ float  g_thr[HEADS * NTOK];    // per-row keep threshold (float)
__device__ float  g_pre[128 * 1024];      // attention output in proj layout [ch][pixel]

// ---------------- kernel 1: qkv = 1x1x1 group conv + depthwise 3x3 ----------------
__global__ void prep_kernel(const float* __restrict__ x,
                            const float* __restrict__ wqkv,
                            const float* __restrict__ wdw) {
    __shared__ float sh[34][34];
    int o  = blockIdx.x;
    int cd = blockIdx.y;
    int tid = threadIdx.x;
    for (int i = tid; i < 34 * 34; i += THREADS) ((float*)sh)[i] = 0.f;
    __syncthreads();
    float w0 = wqkv[o * 4 + 0], w1 = wqkv[o * 4 + 1];
    float w2 = wqkv[o * 4 + 2], w3 = wqkv[o * 4 + 3];
    for (int p = tid; p < 1024; p += THREADS) {
        int y = p >> 5, xx = p & 31;
        float v = w0 * x[(0 * 32 + cd) * 1024 + p]
                + w1 * x[(1 * 32 + cd) * 1024 + p]
                + w2 * x[(2 * 32 + cd) * 1024 + p]
                + w3 * x[(3 * 32 + cd) * 1024 + p];
        sh[y + 1][xx + 1] = v;
    }
    __syncthreads();
    float k00 = wdw[o*9+0], k01 = wdw[o*9+1], k02 = wdw[o*9+2];
    float k10 = wdw[o*9+3], k11 = wdw[o*9+4], k12 = wdw[o*9+5];
    float k20 = wdw[o*9+6], k21 = wdw[o*9+7], k22 = wdw[o*9+8];
    int g = o >> 2, tt = o & 3;
    int head = cd >> 2, c = cd & 3;
    for (int p = tid; p < 1024; p += THREADS) {
        int y = p >> 5, xx = p & 31;
        float s = k00*sh[y  ][xx] + k01*sh[y  ][xx+1] + k02*sh[y  ][xx+2]
                + k10*sh[y+1][xx] + k11*sh[y+1][xx+1] + k12*sh[y+1][xx+2]
                + k20*sh[y+2][xx] + k21*sh[y+2][xx+1] + k22*sh[y+2][xx+2];
        int n = (p << 2) + tt;
        if (g == 0)      g_qraw[cd * NTOK + n] = s;
        else if (g == 1) ((float*)g_kT)[(head * NTOK + n) * 4 + c] = s;
        else             ((float*)g_vT)[(head * NTOK + n) * 4 + c] = s;
    }
}

// ---------------- kernel 2: norms + per-head k stats ----------------
__constant__ int c_pa[10] = {0,0,0,0,1,1,1,2,2,3};
__constant__ int c_pb[10] = {0,1,2,3,1,2,3,2,3,3};

__global__ void norm_kernel() {
    int i = blockIdx.x;
    int tid = threadIdx.x;
    int lane = tid & 31, wid = tid >> 5;
    __shared__ float red[8 * 14];

    if (i < 64) {
        float s = 0.f;
        if (i < 32) {
            const float* q = g_qraw + i * NTOK;
            for (int n = tid; n < NTOK; n += THREADS) { float v = q[n]; s += v * v; }
        } else {
            int j = i - 32; int head = j >> 2, c = j & 3;
            const float* k = ((const float*)g_kT) + head * NTOK * 4 + c;
            for (int n = tid; n < NTOK; n += THREADS) { float v = k[n * 4]; s += v * v; }
        }
        for (int off = 16; off; off >>= 1) s += __shfl_down_sync(0xffffffffu, s, off);
        if (lane == 0) red[wid] = s;
        __syncthreads();
        if (tid == 0) {
            float t = 0.f;
            for (int w = 0; w < 8; w++) t += red[w];
            float scale = 1.f / fmaxf(sqrtf(t), 1e-12f);
            if (i < 32) g_qs[i] = scale; else g_ks[i - 32] = scale;
        }
    } else {
        int head = i - 64;
        const float4* kt = g_kT + head * NTOK;
        float vals[14];
        #pragma unroll
        for (int q = 0; q < 14; q++) vals[q] = 0.f;
        for (int n = tid; n < NTOK; n += THREADS) {
            float4 k = kt[n];
            vals[0] += k.x; vals[1] += k.y; vals[2] += k.z; vals[3] += k.w;
            vals[4]  += k.x*k.x; vals[5]  += k.x*k.y; vals[6]  += k.x*k.z; vals[7] += k.x*k.w;
            vals[8]  += k.y*k.y; vals[9]  += k.y*k.z; vals[10] += k.y*k.w;
            vals[11] += k.z*k.z; vals[12] += k.z*k.w; vals[13] += k.w*k.w;
        }
        #pragma unroll
        for (int q = 0; q < 14; q++)
            for (int off = 16; off; off >>= 1)
                vals[q] += __shfl_down_sync(0xffffffffu, vals[q], off);
        if (lane == 0) {
            #pragma unroll
            for (int q = 0; q < 14; q++) red[wid * 14 + q] = vals[q];
        }
        __syncthreads();
        if (tid < 14) {
            float s = 0.f;
            for (int w = 0; w < 8; w++) s += red[w * 14 + tid];
            s *= (1.f / 4096.f);
            if (tid < 4) g_kmean[head * 4 + tid] = s;
            else {
                int a = c_pa[tid - 4], b = c_pb[tid - 4];
                g_km2[head * 16 + a * 4 + b] = s;
                g_km2[head * 16 + b * 4 + a] = s;
            }
        }
    }
}

// ---------------- shared helpers ----------------
__device__ __forceinline__ unsigned ordkey(float f) {
    unsigned u = __float_as_uint(f);
    return u ^ (0x80000000u | (unsigned)((int)u >> 31));
}
__device__ __forceinline__ float inv_ordkey(unsigned u) {
    return __uint_as_float(u ^ (0x80000000u | ~(unsigned)((int)u >> 31)));
}
__device__ __forceinline__ unsigned next_pivot(unsigned lo, unsigned hi, int clo, int chi, int useInterp) {
    unsigned span = hi - lo;
    unsigned step;
    if (!useInterp) step = span >> 1;
    else {
        float fr = (float)(RANK + 1 - clo) / (float)(chi - clo);
        step = (unsigned)(fr * (float)span);
        unsigned mn = span >> 4; if (!mn) mn = 1;
        if (step < mn) step = mn;
        if (step > span - mn) step = span - mn;
    }
    if (!step) step = 1;
    return lo + step;
}

#define SCORE(cfr, kk) fmaf((cfr).x,(kk).x, fmaf((cfr).y,(kk).y, fmaf((cfr).z,(kk).z, (cfr).w*(kk).w)))

// compute per-row score coefficients (identical FMA chain in both kernels)
__device__ __forceinline__ void row_coeffs(int head, int n0, float temp, float4* cf) {
    #pragma unroll
    for (int r = 0; r < ROWS; r++) {
        int n = n0 + r;
        float a0 = g_qraw[(head*4+0)*NTOK + n] * g_qs[head*4+0] * g_ks[head*4+0] * temp;
        float a1 = g_qraw[(head*4+1)*NTOK + n] * g_qs[head*4+1] * g_ks[head*4+1] * temp;
        float a2 = g_qraw[(head*4+2)*NTOK + n] * g_qs[head*4+2] * g_ks[head*4+2] * temp;
        float a3 = g_qraw[(head*4+3)*NTOK + n] * g_qs[head*4+3] * g_ks[head*4+3] * temp;
        cf[r] = make_float4(a0, a1, a2, a3);
    }
}

// ---------------- kernel 3a: per-row threshold selection ----------------
__global__ void __launch_bounds__(THREADS, 3) select_kernel(const float* __restrict__ temperature) {
    __shared__ unsigned buf[ROWS * 8 * SEG];
    __shared__ unsigned swc[32];               // [warp][row] segment counts
    __shared__ unsigned cnt[4];
    __shared__ unsigned state[4];              // 0=bisect 1=buffer 2=done 3=compact
    __shared__ unsigned slo[4], shi[4];
    __shared__ int      sclo[4], schi[4];
    __shared__ unsigned spiv[4], stkey[4], stgt[4];
    __shared__ unsigned spv1[4], spv5[4];
    __shared__ float    sMb[4];
    __shared__ int      sany[1];
    __shared__ unsigned wred[32];

    int bx   = blockIdx.x;
    int head = bx >> 10;
    int n0   = (bx & 1023) << 2;
    int tid  = threadIdx.x;
    int lane = tid & 31, wid = tid >> 5;

    float temp = temperature[head];
    float4 cf[ROWS];
    row_coeffs(head, n0, temp, cf);

    // analytic per-row pivots (quantiles ~0.165 / ~0.235)
    float p1f[ROWS], p5f[ROWS];
    {
        float mu0 = g_kmean[head*4+0], mu1 = g_kmean[head*4+1];
        float mu2 = g_kmean[head*4+2], mu3 = g_kmean[head*4+3];
        const float* M = g_km2 + head * 16;
        float m00=M[0], m01=M[1], m02=M[2], m03=M[3];
        float m11=M[5], m12=M[6], m13=M[7];
        float m22=M[10], m23=M[11], m33=M[15];
        #pragma unroll
        for (int r = 0; r < ROWS; r++) {
            float cx = cf[r].x, cy = cf[r].y, cz = cf[r].z, cw = cf[r].w;
            float mean = cx*mu0 + cy*mu1 + cz*mu2 + cw*mu3;
            float t0 = m00*cx + m01*cy + m02*cz + m03*cw;
            float t1 = m01*cx + m11*cy + m12*cz + m13*cw;
            float t2 = m02*cx + m12*cy + m22*cz + m23*cw;
            float t3 = m03*cx + m13*cy + m23*cz + m33*cw;
            float es2 = cx*t0 + cy*t1 + cz*t2 + cw*t3;
            float var = es2 - mean * mean;
            float sig = sqrtf(fmaxf(var, 0.f));
            p1f[r] = fmaf(-0.9741f, sig, mean);
            p5f[r] = fmaf(-0.7225f, sig, mean);
        }
    }
    if (tid == 0) {
        #pragma unroll
        for (int r = 0; r < ROWS; r++) {
            spv1[r] = ordkey(p1f[r]);
            spv5[r] = ordkey(p5f[r]);
            sMb[r]  = fabsf(cf[r].x) + fabsf(cf[r].y) + fabsf(cf[r].z) + fabsf(cf[r].w);
            cnt[r]  = 0;
        }
    }
    __syncthreads();

    // pass 1: stream k; count + segmented (atomic-free) compaction
    const float4* kt = g_kT + head * NTOK;
    {
        int c1t[ROWS] = {0,0,0,0};
        unsigned cw[ROWS] = {0,0,0,0};
        unsigned lmask = (1u << lane) - 1u;
        #pragma unroll
        for (int jo = 0; jo < 4; jo++) {
            int mb = (jo << 10) + (tid << 2);
            float4 k0 = __ldg(&kt[mb+0]);
            float4 k1 = __ldg(&kt[mb+1]);
            float4 k2 = __ldg(&kt[mb+2]);
            float4 k3 = __ldg(&kt[mb+3]);
            #pragma unroll
            for (int r = 0; r < ROWS; r++) {
                float s0 = SCORE(cf[r], k0);
                float s1 = SCORE(cf[r], k1);
                float s2 = SCORE(cf[r], k2);
                float s3 = SCORE(cf[r], k3);
                float p1 = p1f[r], p5 = p5f[r];
                c1t[r] += (s0 < p1) + (s1 < p1) + (s2 < p1) + (s3 < p1);
                int wx = (s0 >= p1) & (s0 < p5);
                int wy = (s1 >= p1) & (s1 < p5);
                int wz = (s2 >= p1) & (s2 < p5);
                int ww = (s3 >= p1) & (s3 < p5);
                unsigned bX = __ballot_sync(0xffffffffu, wx);
                unsigned bY = __ballot_sync(0xffffffffu, wy);
                unsigned bZ = __ballot_sync(0xffffffffu, wz);
                unsigned bW = __ballot_sync(0xffffffffu, ww);
                unsigned base = cw[r];
                unsigned* seg = buf + (r * 8 + wid) * SEG;
                if (wx) { unsigned q = base + __popc(bX & lmask); if (q < SEG) seg[q] = ordkey(s0); }
                base += __popc(bX);
                if (wy) { unsigned q = base + __popc(bY & lmask); if (q < SEG) seg[q] = ordkey(s1); }
                base += __popc(bY);
                if (wz) { unsigned q = base + __popc(bZ & lmask); if (q < SEG) seg[q] = ordkey(s2); }
                base += __popc(bZ);
                if (ww) { unsigned q = base + __popc(bW & lmask); if (q < SEG) seg[q] = ordkey(s3); }
                cw[r] = base + __popc(bW);
            }
        }
        #pragma unroll
        for (int r = 0; r < ROWS; r++) c1t[r] = __reduce_add_sync(0xffffffffu, c1t[r]);
        if (lane == 0) {
            #pragma unroll
            for (int r = 0; r < ROWS; r++) {
                wred[wid*4 + r] = (unsigned)c1t[r];
                swc[wid*4 + r]  = cw[r];
            }
        }
    }
    __syncthreads();

    // merge + classify (warps 0..3, one per row)
    if (wid < 4) {
        int r = wid;
        unsigned wc = (lane < 8) ? swc[lane*4 + r] : 0u;
        unsigned ovf = __ballot_sync(0xffffffffu, wc > SEG);
        unsigned tot = __reduce_add_sync(0xffffffffu, wc);
        int c1 = (lane < 8) ? (int)wred[lane*4 + r] : 0;
        c1 = __reduce_add_sync(0xffffffffu, c1);
        int c5 = c1 + (int)tot;
        unsigned* rowbuf = buf + r * 8 * SEG;
        unsigned dbase = 0;
        #pragma unroll 1
        for (int w = 0; w < 8; w++) {
            unsigned c = swc[w*4 + r]; if (c > SEG) c = SEG;
            const unsigned* src = buf + (r * 8 + w) * SEG;
            for (unsigned i = lane; i < c; i += 32) rowbuf[dbase + i] = src[i];
            dbase += c;
            __syncwarp();
        }
        if (lane == 0) {
            unsigned p1 = spv1[r], p5 = spv5[r];
            bool ok = (ovf == 0u) && (c1 <= RANK) && (RANK < c5) && (tot <= CAPR);
            if (ok) {
                state[r] = 1u; slo[r] = p1; shi[r] = p5;
                stgt[r] = (unsigned)(RANK - c1); cnt[r] = tot;
            } else {
                unsigned lo, hi; int clo, chi;
                if (RANK < c1)      { lo = 0u; hi = p1; clo = 0;  chi = c1; }
                else if (RANK < c5) { lo = p1; hi = p5; clo = c1; chi = c5; }
                else                { lo = p5; hi = ordkey(sMb[r]) + 1u; clo = c5; chi = NTOK; }
                slo[r] = lo; shi[r] = hi; sclo[r] = clo; schi[r] = chi;
                if (hi - lo <= 1u)          { stkey[r] = lo; state[r] = 2u; }
                else if (chi - clo <= CAPR) { state[r] = 3u; }
                else { state[r] = 0u; spiv[r] = next_pivot(lo, hi, clo, chi, 1); }
            }
        }
    }

    // fallback bisect loop (rare)
    for (int iter = 0; iter < 72; iter++) {
        __syncthreads();
        if (tid == 0)
            sany[0] = (state[0]==0) | (state[1]==0) | (state[2]==0) | (state[3]==0);
        __syncthreads();
        if (!sany[0]) break;
        float pvf[ROWS]; int act[ROWS];
        #pragma unroll
        for (int r = 0; r < ROWS; r++) { act[r] = (state[r] == 0); pvf[r] = inv_ordkey(spiv[r]); }
        int cr[ROWS] = {0,0,0,0};
        #pragma unroll 1
        for (int jo = 0; jo < 4; jo++) {
            int mb = (jo << 10) + (tid << 2);
            float4 k0 = __ldg(&kt[mb+0]);
            float4 k1 = __ldg(&kt[mb+1]);
            float4 k2 = __ldg(&kt[mb+2]);
            float4 k3 = __ldg(&kt[mb+3]);
            #pragma unroll
            for (int r = 0; r < ROWS; r++) {
                if (act[r]) {
                    float s0 = SCORE(cf[r], k0);
                    float s1 = SCORE(cf[r], k1);
                    float s2 = SCORE(cf[r], k2);
                    float s3 = SCORE(cf[r], k3);
                    cr[r] += (s0 < pvf[r]) + (s1 < pvf[r]) + (s2 < pvf[r]) + (s3 < pvf[r]);
                }
            }
        }
        #pragma unroll
        for (int r = 0; r < ROWS; r++) cr[r] = __reduce_add_sync(0xffffffffu, cr[r]);
        if (lane == 0) {
            #pragma unroll
            for (int r = 0; r < ROWS; r++) wred[wid*4 + r] = (unsigned)cr[r];
        }
        __syncthreads();
        if (tid < 4 && state[tid] == 0) {
            int tot = 0;
            for (int w = 0; w < 8; w++) tot += (int)wred[w*4 + tid];
            if (tot <= RANK) { slo[tid] = spiv[tid]; sclo[tid] = tot; }
            else             { shi[tid] = spiv[tid]; schi[tid] = tot; }
            unsigned lo = slo[tid], hi = shi[tid];
            int cc = schi[tid] - sclo[tid];
            if (hi - lo <= 1u)      { stkey[tid] = lo; state[tid] = 2; }
            else if (cc <= CAPR)    { state[tid] = 3; }
            else spiv[tid] = next_pivot(lo, hi, sclo[tid], schi[tid], !(iter & 1));
        }
    }
    __syncthreads();
    if (tid < 4) {
        if (state[tid] == 0) { stkey[tid] = slo[tid]; state[tid] = 2; } // safety
        if (state[tid] == 3) cnt[tid] = 0;
    }
    __syncthreads();

    // fallback compaction (rare)
    {
        bool anyc = (state[0]==3) | (state[1]==3) | (state[2]==3) | (state[3]==3);
        if (anyc) {
            #pragma unroll 1
            for (int r = 0; r < ROWS; r++) {
                if (state[r] == 3) {
                    float lof = inv_ordkey(slo[r]);
                    float hif = inv_ordkey(shi[r]);
                    #pragma unroll 1
                    for (int jo = 0; jo < 4; jo++) {
                        int mb = (jo << 10) + (tid << 2);
                        float4 k0 = __ldg(&kt[mb+0]);
                        float4 k1 = __ldg(&kt[mb+1]);
                        float4 k2 = __ldg(&kt[mb+2]);
                        float4 k3 = __ldg(&kt[mb+3]);
                        float s0 = SCORE(cf[r], k0);
                        float s1 = SCORE(cf[r], k1);
                        float s2 = SCORE(cf[r], k2);
                        float s3 = SCORE(cf[r], k3);
                        int wx = (s0 >= lof) & (s0 < hif);
                        int wy = (s1 >= lof) & (s1 < hif);
                        int wz = (s2 >= lof) & (s2 < hif);
                        int ww = (s3 >= lof) & (s3 < hif);
                        int nc = wx + wy + wz + ww;
                        if (nc) {
                            unsigned bs = atomicAdd(&cnt[r], (unsigned)nc);
                            if (bs + (unsigned)nc <= CAPR) {
                                unsigned p = bs;
                                unsigned* rb = buf + r * 8 * SEG;
                                if (wx) rb[p++] = ordkey(s0);
                                if (wy) rb[p++] = ordkey(s1);
                                if (wz) rb[p++] = ordkey(s2);
                                if (ww) rb[p++] = ordkey(s3);
                            }
                        }
                    }
                }
            }
            __syncthreads();
            if (tid < 4 && state[tid] == 3) {
                stgt[tid] = (unsigned)(RANK - sclo[tid]);
                state[tid] = 1;
            }
            __syncthreads();
        }
    }

    // warp-register bisect over compacted candidates (1 warp / row), write threshold
    if (wid < 4) {
        int r = wid;
        if (state[r] == 1) {
            int c = (int)cnt[r]; if (c > CAPR) c = CAPR;
            const unsigned* rb = buf + r * 8 * SEG;
            unsigned cand[NREG];
            #pragma unroll
            for (int i = 0; i < NREG; i++) {
                int idx = i * 32 + lane;
                cand[i] = (idx < c) ? rb[idx] : 0xFFFFFFFFu;
            }
            unsigned lo = slo[r], hi = shi[r], tgt = stgt[r];
            while (hi - lo > 1u) {
                unsigned mid = lo + ((hi - lo) >> 1);
                unsigned cb = 0;
                #pragma unroll
                for (int i = 0; i < NREG; i++) cb += (cand[i] < mid);
                cb = __reduce_add_sync(0xffffffffu, cb);
                if (cb <= tgt) lo = mid; else hi = mid;
            }
            if (lane == 0) stkey[r] = lo;
        }
        if (lane == 0) g_thr[head * NTOK + n0 + r] = inv_ordkey(stkey[r]);
    }
}

// ---------------- kernel 3b: masked softmax + p@v (branch-free streaming) ----------------
__global__ void __launch_bounds__(THREADS, 3) apply_kernel(const float* __restrict__ temperature) {
    __shared__ float sred[160];
    __shared__ float sfin[20];

    int bx   = blockIdx.x;
    int head = bx >> 10;
    int n0   = (bx & 1023) << 2;
    int tid  = threadIdx.x;
    int lane = tid & 31, wid = tid >> 5;

    float temp = temperature[head];
    float4 cf[ROWS];
    row_coeffs(head, n0, temp, cf);
    float thrf[ROWS];
    #pragma unroll
    for (int r = 0; r < ROWS; r++) thrf[r] = g_thr[head * NTOK + n0 + r];

    float zz[ROWS] = {0.f, 0.f, 0.f, 0.f};
    float4 acc[ROWS];
    #pragma unroll
    for (int r = 0; r < ROWS; r++) acc[r] = make_float4(0.f, 0.f, 0.f, 0.f);
    const float4* kt = g_kT + head * NTOK;
    const float4* vt = g_vT + head * NTOK;
    #pragma unroll
    for (int jo = 0; jo < 4; jo++) {
        #pragma unroll
        for (int hh = 0; hh < 2; hh++) {
            int m = (jo << 10) + (tid << 2) + hh * 2;
            float4 k0 = __ldg(&kt[m+0]);
            float4 k1 = __ldg(&kt[m+1]);
            float4 v0 = __ldg(&vt[m+0]);
            float4 v1 = __ldg(&vt[m+1]);
            #pragma unroll
            for (int r = 0; r < ROWS; r++) {
                float s0 = SCORE(cf[r], k0);
                float s1 = SCORE(cf[r], k1);
                float w0 = (s0 >= thrf[r]) ? __expf(s0) : 0.f;
                float w1 = (s1 >= thrf[r]) ? __expf(s1) : 0.f;
                zz[r] += w0 + w1;
                acc[r].x += w0*v0.x + w1*v1.x;
                acc[r].y += w0*v0.y + w1*v1.y;
                acc[r].z += w0*v0.z + w1*v1.z;
                acc[r].w += w0*v0.w + w1*v1.w;
            }
        }
    }

    // block-reduce 20 accumulators
    float vals[20];
    #pragma unroll
    for (int r = 0; r < ROWS; r++) {
        vals[r*5 + 0] = zz[r];
        vals[r*5 + 1] = acc[r].x; vals[r*5 + 2] = acc[r].y;
        vals[r*5 + 3] = acc[r].z; vals[r*5 + 4] = acc[r].w;
    }
    #pragma unroll
    for (int q = 0; q < 20; q++)
        for (int off = 16; off; off >>= 1)
            vals[q] += __shfl_down_sync(0xffffffffu, vals[q], off);
    if (lane == 0) {
        #pragma unroll
        for (int q = 0; q < 20; q++) sred[q*8 + wid] = vals[q];
    }
    __syncthreads();
    if (tid < 20) {
        float s = 0.f;
        for (int w = 0; w < 8; w++) s += sred[tid*8 + w];
        sfin[tid] = s;
    }
    __syncthreads();
    if (tid < 16) {
        int r = tid >> 2, c = tid & 3;
        float val = sfin[r*5 + 1 + c] / sfin[r*5 + 0];
        int n = n0 + r;
        int tt = n & 3, pixel = n >> 2;
        int ch = tt * 32 + head * 4 + c;
        g_pre[ch * 1024 + pixel] = val;
    }
}

// ---------------- kernel 4: final 1x1 projection ----------------
__global__ void proj_kernel(const float* __restrict__ wproj, float* __restrict__ out) {
    int idx = blockIdx.x * THREADS + threadIdx.x;
    int o = idx >> 10, p = idx & 1023;
    const float* w = wproj + o * 128;
    float s = 0.f;
    #pragma unroll 8
    for (int ch = 0; ch < 128; ch++) s += w[ch] * g_pre[ch * 1024 + p];
    out[idx] = s;
}

// ---------------- launch ----------------
extern "C" void kernel_launch(void* const* d_in, const int* in_sizes, int n_in,
                              void* d_out, int out_size) {
    (void)in_sizes; (void)n_in; (void)out_size;
    const float* x           = (const float*)d_in[0];
    const float* temperature = (const float*)d_in[1];
    const float* wqkv        = (const float*)d_in[2];
    const float* wdw         = (const float*)d_in[3];
    const float* wproj       = (const float*)d_in[4];
    float* out = (float*)d_out;

    prep_kernel<<<dim3(12, 32), THREADS>>>(x, wqkv, wdw);
    norm_kernel<<<72, THREADS>>>();
    select_kernel<<<HEADS * (NTOK / ROWS), THREADS>>>(temperature);
    apply_kernel<<<HEADS * (NTOK / ROWS), THREADS>>>(temperature);
    proj_kernel<<<(128 * 1024) / THREADS, THREADS>>>(wproj, out);
}

// round 16
// speedup vs baseline: 1.4797x; 1.2303x over previous
#include <cuda_runtime.h>

#define HEADS   8
#define NTOK    4096
#define RANK    820        /* # elements strictly below threshold */
#define ROWS    8
#define THREADS 256
#define CAPR    384        /* max candidates for register bisect */
#define NREG    12         /* CAPR/32 */

// ---------------- device scratch ----------------
__device__ float  g_qraw[32 * NTOK];      // [head*4+c][n]
__device__ float4 g_kT  [HEADS * NTOK];   // [head][n] -> (c0,c1,c2,c3)
__device__ float4 g_vT  [HEADS * NTOK];
__device__ float  g_qs[32];
__device__ float  g_ks[32];
__device__ float  g_kmean[HEADS * 4];
__device__ float  g_km2[HEADS * 16];
__device__ float  g_thr[HEADS * NTOK];    // per-row keep threshold (float)
__device__ float  g_pre[128 * 1024];      // attention output in proj layout [ch][pixel]

// ---------------- kernel 1: qkv = 1x1x1 group conv + depthwise 3x3 ----------------
__global__ void prep_kernel(const float* __restrict__ x,
                            const float* __restrict__ wqkv,
                            const float* __restrict__ wdw) {
    __shared__ float sh[34][34];
    int o  = blockIdx.x;
    int cd = blockIdx.y;
    int tid = threadIdx.x;
    for (int i = tid; i < 34 * 34; i += THREADS) ((float*)sh)[i] = 0.f;
    __syncthreads();
    float w0 = wqkv[o * 4 + 0], w1 = wqkv[o * 4 + 1];
    float w2 = wqkv[o * 4 + 2], w3 = wqkv[o * 4 + 3];
    for (int p = tid; p < 1024; p += THREADS) {
        int y = p >> 5, xx = p & 31;
        float v = w0 * x[(0 * 32 + cd) * 1024 + p]
                + w1 * x[(1 * 32 + cd) * 1024 + p]
                + w2 * x[(2 * 32 + cd) * 1024 + p]
                + w3 * x[(3 * 32 + cd) * 1024 + p];
        sh[y + 1][xx + 1] = v;
    }
    __syncthreads();
    float k00 = wdw[o*9+0], k01 = wdw[o*9+1], k02 = wdw[o*9+2];
    float k10 = wdw[o*9+3], k11 = wdw[o*9+4], k12 = wdw[o*9+5];
    float k20 = wdw[o*9+6], k21 = wdw[o*9+7], k22 = wdw[o*9+8];
    int g = o >> 2, tt = o & 3;
    int head = cd >> 2, c = cd & 3;
    for (int p = tid; p < 1024; p += THREADS) {
        int y = p >> 5, xx = p & 31;
        float s = k00*sh[y  ][xx] + k01*sh[y  ][xx+1] + k02*sh[y  ][xx+2]
                + k10*sh[y+1][xx] + k11*sh[y+1][xx+1] + k12*sh[y+1][xx+2]
                + k20*sh[y+2][xx] + k21*sh[y+2][xx+1] + k22*sh[y+2][xx+2];
        int n = (p << 2) + tt;
        if (g == 0)      g_qraw[cd * NTOK + n] = s;
        else if (g == 1) ((float*)g_kT)[(head * NTOK + n) * 4 + c] = s;
        else             ((float*)g_vT)[(head * NTOK + n) * 4 + c] = s;
    }
}

// ---------------- kernel 2: norms + per-head k stats ----------------
__constant__ int c_pa[10] = {0,0,0,0,1,1,1,2,2,3};
__constant__ int c_pb[10] = {0,1,2,3,1,2,3,2,3,3};

__global__ void norm_kernel() {
    int i = blockIdx.x;
    int tid = threadIdx.x;
    int lane = tid & 31, wid = tid >> 5;
    __shared__ float red[8 * 14];

    if (i < 64) {
        float s = 0.f;
        if (i < 32) {
            const float* q = g_qraw + i * NTOK;
            for (int n = tid; n < NTOK; n += THREADS) { float v = q[n]; s += v * v; }
        } else {
            int j = i - 32; int head = j >> 2, c = j & 3;
            const float* k = ((const float*)g_kT) + head * NTOK * 4 + c;
            for (int n = tid; n < NTOK; n += THREADS) { float v = k[n * 4]; s += v * v; }
        }
        for (int off = 16; off; off >>= 1) s += __shfl_down_sync(0xffffffffu, s, off);
        if (lane == 0) red[wid] = s;
        __syncthreads();
        if (tid == 0) {
            float t = 0.f;
            for (int w = 0; w < 8; w++) t += red[w];
            float scale = 1.f / fmaxf(sqrtf(t), 1e-12f);
            if (i < 32) g_qs[i] = scale; else g_ks[i - 32] = scale;
        }
    } else {
        int head = i - 64;
        const float4* kt = g_kT + head * NTOK;
        float vals[14];
        #pragma unroll
        for (int q = 0; q < 14; q++) vals[q] = 0.f;
        for (int n = tid; n < NTOK; n += THREADS) {
            float4 k = kt[n];
            vals[0] += k.x; vals[1] += k.y; vals[2] += k.z; vals[3] += k.w;
            vals[4]  += k.x*k.x; vals[5]  += k.x*k.y; vals[6]  += k.x*k.z; vals[7] += k.x*k.w;
            vals[8]  += k.y*k.y; vals[9]  += k.y*k.z; vals[10] += k.y*k.w;
            vals[11] += k.z*k.z; vals[12] += k.z*k.w; vals[13] += k.w*k.w;
        }
        #pragma unroll
        for (int q = 0; q < 14; q++)
            for (int off = 16; off; off >>= 1)
                vals[q] += __shfl_down_sync(0xffffffffu, vals[q], off);
        if (lane == 0) {
            #pragma unroll
            for (int q = 0; q < 14; q++) red[wid * 14 + q] = vals[q];
        }
        __syncthreads();
        if (tid < 14) {
            float s = 0.f;
            for (int w = 0; w < 8; w++) s += red[w * 14 + tid];
            s *= (1.f / 4096.f);
            if (tid < 4) g_kmean[head * 4 + tid] = s;
            else {
                int a = c_pa[tid - 4], b = c_pb[tid - 4];
                g_km2[head * 16 + a * 4 + b] = s;
                g_km2[head * 16 + b * 4 + a] = s;
            }
        }
    }
}

// ---------------- shared helpers ----------------
__device__ __forceinline__ unsigned ordkey(float f) {
    unsigned u = __float_as_uint(f);
    return u ^ (0x80000000u | (unsigned)((int)u >> 31));
}
__device__ __forceinline__ float inv_ordkey(unsigned u) {
    return __uint_as_float(u ^ (0x80000000u | ~(unsigned)((int)u >> 31)));
}
__device__ __forceinline__ unsigned next_pivot(unsigned lo, unsigned hi, int clo, int chi, int useInterp) {
    unsigned span = hi - lo;
    unsigned step;
    if (!useInterp) step = span >> 1;
    else {
        float fr = (float)(RANK + 1 - clo) / (float)(chi - clo);
        step = (unsigned)(fr * (float)span);
        unsigned mn = span >> 4; if (!mn) mn = 1;
        if (step < mn) step = mn;
        if (step > span - mn) step = span - mn;
    }
    if (!step) step = 1;
    return lo + step;
}

#define SCORE(cfr, kk) fmaf((cfr).x,(kk).x, fmaf((cfr).y,(kk).y, fmaf((cfr).z,(kk).z, (cfr).w*(kk).w)))

// per-row score coefficients (identical FMA chain in both kernels)
__device__ __forceinline__ void row_coeffs(int head, int n0, float temp, float4* cf) {
    #pragma unroll
    for (int r = 0; r < ROWS; r++) {
        int n = n0 + r;
        float a0 = g_qraw[(head*4+0)*NTOK + n] * g_qs[head*4+0] * g_ks[head*4+0] * temp;
        float a1 = g_qraw[(head*4+1)*NTOK + n] * g_qs[head*4+1] * g_ks[head*4+1] * temp;
        float a2 = g_qraw[(head*4+2)*NTOK + n] * g_qs[head*4+2] * g_ks[head*4+2] * temp;
        float a3 = g_qraw[(head*4+3)*NTOK + n] * g_qs[head*4+3] * g_ks[head*4+3] * temp;
        cf[r] = make_float4(a0, a1, a2, a3);
    }
}

// ---------------- kernel 3a: per-row threshold selection (8 rows/CTA) ----------------
__global__ void __launch_bounds__(THREADS, 3) select_kernel(const float* __restrict__ temperature) {
    __shared__ unsigned buf[ROWS * CAPR];       // 12 KB
    __shared__ unsigned cnt[ROWS];
    __shared__ unsigned state[ROWS];            // 0=bisect 1=buffer 2=done 3=compact
    __shared__ unsigned slo[ROWS], shi[ROWS];
    __shared__ int      sclo[ROWS], schi[ROWS];
    __shared__ unsigned spiv[ROWS], stkey[ROWS], stgt[ROWS];
    __shared__ float    sMb[ROWS];
    __shared__ int      sany[1];
    __shared__ unsigned wred[64];

    int bx   = blockIdx.x;
    int head = bx >> 9;
    int n0   = (bx & 511) << 3;
    int tid  = threadIdx.x;
    int lane = tid & 31, wid = tid >> 5;

    float temp = temperature[head];
    float4 cf[ROWS];
    row_coeffs(head, n0, temp, cf);

    // analytic per-row pivots (quantiles ~0.165 / ~0.235)
    float p1f[ROWS], p5f[ROWS];
    {
        float mu0 = g_kmean[head*4+0], mu1 = g_kmean[head*4+1];
        float mu2 = g_kmean[head*4+2], mu3 = g_kmean[head*4+3];
        const float* M = g_km2 + head * 16;
        float m00=M[0], m01=M[1], m02=M[2], m03=M[3];
        float m11=M[5], m12=M[6], m13=M[7];
        float m22=M[10], m23=M[11], m33=M[15];
        #pragma unroll
        for (int r = 0; r < ROWS; r++) {
            float cx = cf[r].x, cy = cf[r].y, cz = cf[r].z, cw = cf[r].w;
            float mean = cx*mu0 + cy*mu1 + cz*mu2 + cw*mu3;
            float t0 = m00*cx + m01*cy + m02*cz + m03*cw;
            float t1 = m01*cx + m11*cy + m12*cz + m13*cw;
            float t2 = m02*cx + m12*cy + m22*cz + m23*cw;
            float t3 = m03*cx + m13*cy + m23*cz + m33*cw;
            float es2 = cx*t0 + cy*t1 + cz*t2 + cw*t3;
            float var = es2 - mean * mean;
            float sig = sqrtf(fmaxf(var, 0.f));
            p1f[r] = fmaf(-0.9741f, sig, mean);
            p5f[r] = fmaf(-0.7225f, sig, mean);
        }
    }
    if (tid == 0) {
        #pragma unroll
        for (int r = 0; r < ROWS; r++) {
            sMb[r] = fabsf(cf[r].x) + fabsf(cf[r].y) + fabsf(cf[r].z) + fabsf(cf[r].w);
            cnt[r] = 0;
        }
    }
    __syncthreads();

    // pass 1: stream k once; count below p1 + compact window via per-thread atomics
    const float4* kt = g_kT + head * NTOK;
    {
        int c1t[ROWS];
        #pragma unroll
        for (int r = 0; r < ROWS; r++) c1t[r] = 0;
        #pragma unroll
        for (int jo = 0; jo < 4; jo++) {
            int mb = (jo << 10) + (tid << 2);
            float4 k0 = __ldg(&kt[mb+0]);
            float4 k1 = __ldg(&kt[mb+1]);
            float4 k2 = __ldg(&kt[mb+2]);
            float4 k3 = __ldg(&kt[mb+3]);
            #pragma unroll
            for (int r = 0; r < ROWS; r++) {
                float s0 = SCORE(cf[r], k0);
                float s1 = SCORE(cf[r], k1);
                float s2 = SCORE(cf[r], k2);
                float s3 = SCORE(cf[r], k3);
                float p1 = p1f[r], p5 = p5f[r];
                c1t[r] += (s0 < p1) + (s1 < p1) + (s2 < p1) + (s3 < p1);
                int wx = (s0 >= p1) & (s0 < p5);
                int wy = (s1 >= p1) & (s1 < p5);
                int wz = (s2 >= p1) & (s2 < p5);
                int ww = (s3 >= p1) & (s3 < p5);
                int nc = wx + wy + wz + ww;
                if (nc) {
                    unsigned bs = atomicAdd(&cnt[r], (unsigned)nc);
                    if (bs + (unsigned)nc <= CAPR) {
                        unsigned p = bs;
                        unsigned* rb = buf + r * CAPR;
                        if (wx) rb[p++] = ordkey(s0);
                        if (wy) rb[p++] = ordkey(s1);
                        if (wz) rb[p++] = ordkey(s2);
                        if (ww) rb[p++] = ordkey(s3);
                    }
                }
            }
        }
        #pragma unroll
        for (int r = 0; r < ROWS; r++) c1t[r] = __reduce_add_sync(0xffffffffu, c1t[r]);
        if (lane == 0) {
            #pragma unroll
            for (int r = 0; r < ROWS; r++) wred[wid*8 + r] = (unsigned)c1t[r];
        }
    }
    __syncthreads();

    // classify rows
    if (tid < ROWS) {
        int c1v = 0;
        for (int w = 0; w < 8; w++) c1v += (int)wred[w*8 + tid];
        int cw  = (int)cnt[tid];
        int c5v = c1v + cw;
        unsigned p1 = ordkey(p1f[tid]), p5 = ordkey(p5f[tid]);
        if (c1v <= RANK && RANK < c5v && cw <= CAPR) {
            state[tid] = 1u; slo[tid] = p1; shi[tid] = p5;
            stgt[tid] = (unsigned)(RANK - c1v);
        } else {
            unsigned lo, hi; int clo, chi;
            if (RANK < c1v)      { lo = 0u; hi = p1; clo = 0;   chi = c1v; }
            else if (RANK < c5v) { lo = p1; hi = p5; clo = c1v; chi = c5v; }
            else                 { lo = p5; hi = ordkey(sMb[tid]) + 1u; clo = c5v; chi = NTOK; }
            slo[tid] = lo; shi[tid] = hi; sclo[tid] = clo; schi[tid] = chi;
            if (hi - lo <= 1u)          { stkey[tid] = lo; state[tid] = 2u; }
            else if (chi - clo <= CAPR) { state[tid] = 3u; }
            else { state[tid] = 0u; spiv[tid] = next_pivot(lo, hi, clo, chi, 1); }
        }
    }

    // fallback bisect loop (rare): recompute from k
    for (int iter = 0; iter < 72; iter++) {
        __syncthreads();
        if (tid == 0) {
            int a = 0;
            #pragma unroll
            for (int r = 0; r < ROWS; r++) a |= (state[r] == 0);
            sany[0] = a;
        }
        __syncthreads();
        if (!sany[0]) break;
        float pvf[ROWS]; int act[ROWS];
        #pragma unroll
        for (int r = 0; r < ROWS; r++) { act[r] = (state[r] == 0); pvf[r] = inv_ordkey(spiv[r]); }
        int cr[ROWS];
        #pragma unroll
        for (int r = 0; r < ROWS; r++) cr[r] = 0;
        #pragma unroll 1
        for (int jo = 0; jo < 4; jo++) {
            int mb = (jo << 10) + (tid << 2);
            float4 k0 = __ldg(&kt[mb+0]);
            float4 k1 = __ldg(&kt[mb+1]);
            float4 k2 = __ldg(&kt[mb+2]);
            float4 k3 = __ldg(&kt[mb+3]);
            #pragma unroll
            for (int r = 0; r < ROWS; r++) {
                if (act[r]) {
                    float s0 = SCORE(cf[r], k0);
                    float s1 = SCORE(cf[r], k1);
                    float s2 = SCORE(cf[r], k2);
                    float s3 = SCORE(cf[r], k3);
                    cr[r] += (s0 < pvf[r]) + (s1 < pvf[r]) + (s2 < pvf[r]) + (s3 < pvf[r]);
                }
            }
        }
        #pragma unroll
        for (int r = 0; r < ROWS; r++) cr[r] = __reduce_add_sync(0xffffffffu, cr[r]);
        if (lane == 0) {
            #pragma unroll
            for (int r = 0; r < ROWS; r++) wred[wid*8 + r] = (unsigned)cr[r];
        }
        __syncthreads();
        if (tid < ROWS && state[tid] == 0) {
            int tot = 0;
            for (int w = 0; w < 8; w++) tot += (int)wred[w*8 + tid];
            if (tot <= RANK) { slo[tid] = spiv[tid]; sclo[tid] = tot; }
            else             { shi[tid] = spiv[tid]; schi[tid] = tot; }
            unsigned lo = slo[tid], hi = shi[tid];
            int cc = schi[tid] - sclo[tid];
            if (hi - lo <= 1u)      { stkey[tid] = lo; state[tid] = 2; }
            else if (cc <= CAPR)    { state[tid] = 3; }
            else spiv[tid] = next_pivot(lo, hi, sclo[tid], schi[tid], !(iter & 1));
        }
    }
    __syncthreads();
    if (tid < ROWS) {
        if (state[tid] == 0) { stkey[tid] = slo[tid]; state[tid] = 2; } // safety
        if (state[tid] == 3) cnt[tid] = 0;
    }
    __syncthreads();

    // fallback compaction (rare): recompute from k
    {
        int anyc = 0;
        #pragma unroll
        for (int r = 0; r < ROWS; r++) anyc |= (state[r] == 3);
        if (anyc) {
            #pragma unroll 1
            for (int r = 0; r < ROWS; r++) {
                if (state[r] == 3) {
                    float lof = inv_ordkey(slo[r]);
                    float hif = inv_ordkey(shi[r]);
                    #pragma unroll 1
                    for (int jo = 0; jo < 4; jo++) {
                        int mb = (jo << 10) + (tid << 2);
                        float4 k0 = __ldg(&kt[mb+0]);
                        float4 k1 = __ldg(&kt[mb+1]);
                        float4 k2 = __ldg(&kt[mb+2]);
                        float4 k3 = __ldg(&kt[mb+3]);
                        float s0 = SCORE(cf[r], k0);
                        float s1 = SCORE(cf[r], k1);
                        float s2 = SCORE(cf[r], k2);
                        float s3 = SCORE(cf[r], k3);
                        int wx = (s0 >= lof) & (s0 < hif);
                        int wy = (s1 >= lof) & (s1 < hif);
                        int wz = (s2 >= lof) & (s2 < hif);
                        int ww = (s3 >= lof) & (s3 < hif);
                        int nc = wx + wy + wz + ww;
                        if (nc) {
                            unsigned bs = atomicAdd(&cnt[r], (unsigned)nc);
                            if (bs + (unsigned)nc <= CAPR) {
                                unsigned p = bs;
                                unsigned* rb = buf + r * CAPR;
                                if (wx) rb[p++] = ordkey(s0);
                                if (wy) rb[p++] = ordkey(s1);
                                if (wz) rb[p++] = ordkey(s2);
                                if (ww) rb[p++] = ordkey(s3);
                            }
                        }
                    }
                }
            }
            __syncthreads();
            if (tid < ROWS && state[tid] == 3) {
                stgt[tid] = (unsigned)(RANK - sclo[tid]);
                state[tid] = 1;
            }
            __syncthreads();
        }
    }

    // warp-register bisect (1 warp / row, all 8 warps), write threshold
    {
        int r = wid;
        if (state[r] == 1) {
            int c = (int)cnt[r]; if (c > CAPR) c = CAPR;
            const unsigned* rb = buf + r * CAPR;
            unsigned cand[NREG];
            #pragma unroll
            for (int i = 0; i < NREG; i++) {
                int idx = i * 32 + lane;
                cand[i] = (idx < c) ? rb[idx] : 0xFFFFFFFFu;
            }
            unsigned lo = slo[r], hi = shi[r], tgt = stgt[r];
            while (hi - lo > 1u) {
                unsigned mid = lo + ((hi - lo) >> 1);
                unsigned cb = 0;
                #pragma unroll
                for (int i = 0; i < NREG; i++) cb += (cand[i] < mid);
                cb = __reduce_add_sync(0xffffffffu, cb);
                if (cb <= tgt) lo = mid; else hi = mid;
            }
            if (lane == 0) stkey[r] = lo;
        }
        __syncwarp();
        if (lane == 0) g_thr[head * NTOK + n0 + r] = inv_ordkey(stkey[r]);
    }
}

// ---------------- kernel 3b: masked softmax + p@v (8 rows/CTA streaming) ----------------
__global__ void __launch_bounds__(THREADS, 2) apply_kernel(const float* __restrict__ temperature) {
    __shared__ float sred[40 * 8];
    __shared__ float sfin[40];

    int bx   = blockIdx.x;
    int head = bx >> 9;
    int n0   = (bx & 511) << 3;
    int tid  = threadIdx.x;
    int lane = tid & 31, wid = tid >> 5;

    float temp = temperature[head];
    float4 cf[ROWS];
    row_coeffs(head, n0, temp, cf);
    float thrf[ROWS];
    #pragma unroll
    for (int r = 0; r < ROWS; r++) thrf[r] = g_thr[head * NTOK + n0 + r];

    float zz[ROWS];
    float4 acc[ROWS];
    #pragma unroll
    for (int r = 0; r < ROWS; r++) { zz[r] = 0.f; acc[r] = make_float4(0.f, 0.f, 0.f, 0.f); }
    const float4* kt = g_kT + head * NTOK;
    const float4* vt = g_vT + head * NTOK;
    #pragma unroll
    for (int jo = 0; jo < 4; jo++) {
        #pragma unroll
        for (int hh = 0; hh < 2; hh++) {
            int m = (jo << 10) + (tid << 2) + hh * 2;
            float4 k0 = __ldg(&kt[m+0]);
            float4 k1 = __ldg(&kt[m+1]);
            float4 v0 = __ldg(&vt[m+0]);
            float4 v1 = __ldg(&vt[m+1]);
            #pragma unroll
            for (int r = 0; r < ROWS; r++) {
                float s0 = SCORE(cf[r], k0);
                float s1 = SCORE(cf[r], k1);
                float w0 = (s0 >= thrf[r]) ? __expf(s0) : 0.f;
                float w1 = (s1 >= thrf[r]) ? __expf(s1) : 0.f;
                zz[r] += w0 + w1;
                acc[r].x += w0*v0.x + w1*v1.x;
                acc[r].y += w0*v0.y + w1*v1.y;
                acc[r].z += w0*v0.z + w1*v1.z;
                acc[r].w += w0*v0.w + w1*v1.w;
            }
        }
    }

    // block-reduce 40 accumulators
    float vals[40];
    #pragma unroll
    for (int r = 0; r < ROWS; r++) {
        vals[r*5 + 0] = zz[r];
        vals[r*5 + 1] = acc[r].x; vals[r*5 + 2] = acc[r].y;
        vals[r*5 + 3] = acc[r].z; vals[r*5 + 4] = acc[r].w;
    }
    #pragma unroll
    for (int q = 0; q < 40; q++)
        for (int off = 16; off; off >>= 1)
            vals[q] += __shfl_down_sync(0xffffffffu, vals[q], off);
    if (lane == 0) {
        #pragma unroll
        for (int q = 0; q < 40; q++) sred[q*8 + wid] = vals[q];
    }
    __syncthreads();
    if (tid < 40) {
        float s = 0.f;
        for (int w = 0; w < 8; w++) s += sred[tid*8 + w];
        sfin[tid] = s;
    }
    __syncthreads();
    if (tid < 32) {
        int r = tid >> 2, c = tid & 3;
        float val = sfin[r*5 + 1 + c] / sfin[r*5 + 0];
        int n = n0 + r;
        int tt = n & 3, pixel = n >> 2;
        int ch = tt * 32 + head * 4 + c;
        g_pre[ch * 1024 + pixel] = val;
    }
}

// ---------------- kernel 4: final 1x1 projection ----------------
__global__ void proj_kernel(const float* __restrict__ wproj, float* __restrict__ out) {
    int idx = blockIdx.x * THREADS + threadIdx.x;
    int o = idx >> 10, p = idx & 1023;
    const float* w = wproj + o * 128;
    float s = 0.f;
    #pragma unroll 8
    for (int ch = 0; ch < 128; ch++) s += w[ch] * g_pre[ch * 1024 + p];
    out[idx] = s;
}

// ---------------- launch ----------------
extern "C" void kernel_launch(void* const* d_in, const int* in_sizes, int n_in,
                              void* d_out, int out_size) {
    (void)in_sizes; (void)n_in; (void)out_size;
    const float* x           = (const float*)d_in[0];
    const float* temperature = (const float*)d_in[1];
    const float* wqkv        = (const float*)d_in[2];
    const float* wdw         = (const float*)d_in[3];
    const float* wproj       = (const float*)d_in[4];
    float* out = (float*)d_out;

    prep_kernel<<<dim3(12, 32), THREADS>>>(x, wqkv, wdw);
    norm_kernel<<<72, THREADS>>>();
    select_kernel<<<HEADS * (NTOK / ROWS), THREADS>>>(temperature);
    apply_kernel<<<HEADS * (NTOK / ROWS), THREADS>>>(temperature);
    proj_kernel<<<(128 * 1024) / THREADS, THREADS>>>(wproj, out);
}

// round 17
// speedup vs baseline: 1.5566x; 1.0519x over previous
#include <cuda_runtime.h>

#define HEADS   8
#define NTOK    4096
#define RANK    820        /* # elements strictly below threshold */
#define ROWS    8          /* rows per CTA (4 per warp-half) */
#define THREADS 256
#define CAPR    384        /* max candidates for register bisect */
#define NREG    12         /* CAPR/32 */

// ---------------- device scratch ----------------
__device__ float  g_qraw[32 * NTOK];      // [head*4+c][n]
__device__ float4 g_kT  [HEADS * NTOK];   // [head][n] -> (c0,c1,c2,c3)
__device__ float4 g_vT  [HEADS * NTOK];
__device__ float  g_qs[32];
__device__ float  g_ks[32];
__device__ float  g_kmean[HEADS * 4];
__device__ float  g_km2[HEADS * 16];
__device__ float  g_thr[HEADS * NTOK];    // per-row keep threshold (float)
__device__ float  g_pre[128 * 1024];      // attention output in proj layout [ch][pixel]

// ---------------- kernel 1: qkv = 1x1x1 group conv + depthwise 3x3 ----------------
__global__ void prep_kernel(const float* __restrict__ x,
                            const float* __restrict__ wqkv,
                            const float* __restrict__ wdw) {
    __shared__ float sh[34][34];
    int o  = blockIdx.x;
    int cd = blockIdx.y;
    int tid = threadIdx.x;
    for (int i = tid; i < 34 * 34; i += THREADS) ((float*)sh)[i] = 0.f;
    __syncthreads();
    float w0 = wqkv[o * 4 + 0], w1 = wqkv[o * 4 + 1];
    float w2 = wqkv[o * 4 + 2], w3 = wqkv[o * 4 + 3];
    for (int p = tid; p < 1024; p += THREADS) {
        int y = p >> 5, xx = p & 31;
        float v = w0 * x[(0 * 32 + cd) * 1024 + p]
                + w1 * x[(1 * 32 + cd) * 1024 + p]
                + w2 * x[(2 * 32 + cd) * 1024 + p]
                + w3 * x[(3 * 32 + cd) * 1024 + p];
        sh[y + 1][xx + 1] = v;
    }
    __syncthreads();
    float k00 = wdw[o*9+0], k01 = wdw[o*9+1], k02 = wdw[o*9+2];
    float k10 = wdw[o*9+3], k11 = wdw[o*9+4], k12 = wdw[o*9+5];
    float k20 = wdw[o*9+6], k21 = wdw[o*9+7], k22 = wdw[o*9+8];
    int g = o >> 2, tt = o & 3;
    int head = cd >> 2, c = cd & 3;
    for (int p = tid; p < 1024; p += THREADS) {
        int y = p >> 5, xx = p & 31;
        float s = k00*sh[y  ][xx] + k01*sh[y  ][xx+1] + k02*sh[y  ][xx+2]
                + k10*sh[y+1][xx] + k11*sh[y+1][xx+1] + k12*sh[y+1][xx+2]
                + k20*sh[y+2][xx] + k21*sh[y+2][xx+1] + k22*sh[y+2][xx+2];
        int n = (p << 2) + tt;
        if (g == 0)      g_qraw[cd * NTOK + n] = s;
        else if (g == 1) ((float*)g_kT)[(head * NTOK + n) * 4 + c] = s;
        else             ((float*)g_vT)[(head * NTOK + n) * 4 + c] = s;
    }
}

// ---------------- kernel 2: norms + per-head k stats ----------------
__constant__ int c_pa[10] = {0,0,0,0,1,1,1,2,2,3};
__constant__ int c_pb[10] = {0,1,2,3,1,2,3,2,3,3};

__global__ void norm_kernel() {
    int i = blockIdx.x;
    int tid = threadIdx.x;
    int lane = tid & 31, wid = tid >> 5;
    __shared__ float red[8 * 14];

    if (i < 64) {
        float s = 0.f;
        if (i < 32) {
            const float* q = g_qraw + i * NTOK;
            for (int n = tid; n < NTOK; n += THREADS) { float v = q[n]; s += v * v; }
        } else {
            int j = i - 32; int head = j >> 2, c = j & 3;
            const float* k = ((const float*)g_kT) + head * NTOK * 4 + c;
            for (int n = tid; n < NTOK; n += THREADS) { float v = k[n * 4]; s += v * v; }
        }
        for (int off = 16; off; off >>= 1) s += __shfl_down_sync(0xffffffffu, s, off);
        if (lane == 0) red[wid] = s;
        __syncthreads();
        if (tid == 0) {
            float t = 0.f;
            for (int w = 0; w < 8; w++) t += red[w];
            float scale = 1.f / fmaxf(sqrtf(t), 1e-12f);
            if (i < 32) g_qs[i] = scale; else g_ks[i - 32] = scale;
        }
    } else {
        int head = i - 64;
        const float4* kt = g_kT + head * NTOK;
        float vals[14];
        #pragma unroll
        for (int q = 0; q < 14; q++) vals[q] = 0.f;
        for (int n = tid; n < NTOK; n += THREADS) {
            float4 k = kt[n];
            vals[0] += k.x; vals[1] += k.y; vals[2] += k.z; vals[3] += k.w;
            vals[4]  += k.x*k.x; vals[5]  += k.x*k.y; vals[6]  += k.x*k.z; vals[7] += k.x*k.w;
            vals[8]  += k.y*k.y; vals[9]  += k.y*k.z; vals[10] += k.y*k.w;
            vals[11] += k.z*k.z; vals[12] += k.z*k.w; vals[13] += k.w*k.w;
        }
        #pragma unroll
        for (int q = 0; q < 14; q++)
            for (int off = 16; off; off >>= 1)
                vals[q] += __shfl_down_sync(0xffffffffu, vals[q], off);
        if (lane == 0) {
            #pragma unroll
            for (int q = 0; q < 14; q++) red[wid * 14 + q] = vals[q];
        }
        __syncthreads();
        if (tid < 14) {
            float s = 0.f;
            for (int w = 0; w < 8; w++) s += red[w * 14 + tid];
            s *= (1.f / 4096.f);
            if (tid < 4) g_kmean[head * 4 + tid] = s;
            else {
                int a = c_pa[tid - 4], b = c_pb[tid - 4];
                g_km2[head * 16 + a * 4 + b] = s;
                g_km2[head * 16 + b * 4 + a] = s;
            }
        }
    }
}

// ---------------- shared helpers ----------------
__device__ __forceinline__ unsigned ordkey(float f) {
    unsigned u = __float_as_uint(f);
    return u ^ (0x80000000u | (unsigned)((int)u >> 31));
}
__device__ __forceinline__ float inv_ordkey(unsigned u) {
    return __uint_as_float(u ^ (0x80000000u | ~(unsigned)((int)u >> 31)));
}
__device__ __forceinline__ unsigned next_pivot(unsigned lo, unsigned hi, int clo, int chi, int useInterp) {
    unsigned span = hi - lo;
    unsigned step;
    if (!useInterp) step = span >> 1;
    else {
        float fr = (float)(RANK + 1 - clo) / (float)(chi - clo);
        step = (unsigned)(fr * (float)span);
        unsigned mn = span >> 4; if (!mn) mn = 1;
        if (step < mn) step = mn;
        if (step > span - mn) step = span - mn;
    }
    if (!step) step = 1;
    return lo + step;
}

#define SCORE(cfr, kk) fmaf((cfr).x,(kk).x, fmaf((cfr).y,(kk).y, fmaf((cfr).z,(kk).z, (cfr).w*(kk).w)))

// 4-row coefficient block starting at row b0 (bit-identical chain everywhere)
__device__ __forceinline__ void row_coeffs4(int head, int b0, float temp, float4* cf) {
    #pragma unroll
    for (int r = 0; r < 4; r++) {
        int n = b0 + r;
        float a0 = g_qraw[(head*4+0)*NTOK + n] * g_qs[head*4+0] * g_ks[head*4+0] * temp;
        float a1 = g_qraw[(head*4+1)*NTOK + n] * g_qs[head*4+1] * g_ks[head*4+1] * temp;
        float a2 = g_qraw[(head*4+2)*NTOK + n] * g_qs[head*4+2] * g_ks[head*4+2] * temp;
        float a3 = g_qraw[(head*4+3)*NTOK + n] * g_qs[head*4+3] * g_ks[head*4+3] * temp;
        cf[r] = make_float4(a0, a1, a2, a3);
    }
}

// ---------------- kernel 3a: threshold selection (8 rows/CTA, 4 rows per warp-half) ----------------
__global__ void __launch_bounds__(THREADS, 3) select_kernel(const float* __restrict__ temperature) {
    __shared__ unsigned buf[ROWS * CAPR];       // 12 KB
    __shared__ unsigned cnt[ROWS];
    __shared__ unsigned state[ROWS];            // 0=bisect 1=buffer 2=done 3=compact
    __shared__ unsigned slo[ROWS], shi[ROWS];
    __shared__ int      sclo[ROWS], schi[ROWS];
    __shared__ unsigned spiv[ROWS], stkey[ROWS], stgt[ROWS];
    __shared__ float    sMb[ROWS];
    __shared__ unsigned spv1[ROWS], spv5[ROWS];
    __shared__ int      sany[1];
    __shared__ unsigned wred[32];

    int bx   = blockIdx.x;
    int head = bx >> 9;
    int n0   = (bx & 511) << 3;
    int tid  = threadIdx.x;
    int lane = tid & 31, wid = tid >> 5;
    int rg   = wid >> 2;                 // warp-half: 0 -> rows 0..3, 1 -> rows 4..7
    int ht   = tid & 127;                // thread index within half
    int b0   = n0 + rg * 4;

    float temp = temperature[head];
    float4 cf[4];
    row_coeffs4(head, b0, temp, cf);

    // analytic pivots for this half's 4 rows (quantiles ~0.165 / ~0.235)
    float p1f[4], p5f[4];
    {
        float mu0 = g_kmean[head*4+0], mu1 = g_kmean[head*4+1];
        float mu2 = g_kmean[head*4+2], mu3 = g_kmean[head*4+3];
        const float* M = g_km2 + head * 16;
        float m00=M[0], m01=M[1], m02=M[2], m03=M[3];
        float m11=M[5], m12=M[6], m13=M[7];
        float m22=M[10], m23=M[11], m33=M[15];
        #pragma unroll
        for (int r = 0; r < 4; r++) {
            float cx = cf[r].x, cy = cf[r].y, cz = cf[r].z, cw = cf[r].w;
            float mean = cx*mu0 + cy*mu1 + cz*mu2 + cw*mu3;
            float t0 = m00*cx + m01*cy + m02*cz + m03*cw;
            float t1 = m01*cx + m11*cy + m12*cz + m13*cw;
            float t2 = m02*cx + m12*cy + m22*cz + m23*cw;
            float t3 = m03*cx + m13*cy + m23*cz + m33*cw;
            float es2 = cx*t0 + cy*t1 + cz*t2 + cw*t3;
            float var = es2 - mean * mean;
            float sig = sqrtf(fmaxf(var, 0.f));
            p1f[r] = fmaf(-0.9741f, sig, mean);
            p5f[r] = fmaf(-0.7225f, sig, mean);
        }
    }
    if (ht == 0) {   // one writer per half (warp 0 / warp 4, lane 0)
        #pragma unroll
        for (int r = 0; r < 4; r++) {
            int g = rg * 4 + r;
            sMb[g]  = fabsf(cf[r].x) + fabsf(cf[r].y) + fabsf(cf[r].z) + fabsf(cf[r].w);
            spv1[g] = ordkey(p1f[r]);
            spv5[g] = ordkey(p5f[r]);
            cnt[g]  = 0;
        }
    }
    __syncthreads();

    // pass 1: this half streams all tokens for its 4 rows
    const float4* kt = g_kT + head * NTOK;
    {
        int c1t[4] = {0,0,0,0};
        #pragma unroll
        for (int jo = 0; jo < 8; jo++) {
            int mb = (jo << 9) + (ht << 2);
            float4 k0 = __ldg(&kt[mb+0]);
            float4 k1 = __ldg(&kt[mb+1]);
            float4 k2 = __ldg(&kt[mb+2]);
            float4 k3 = __ldg(&kt[mb+3]);
            #pragma unroll
            for (int r = 0; r < 4; r++) {
                float s0 = SCORE(cf[r], k0);
                float s1 = SCORE(cf[r], k1);
                float s2 = SCORE(cf[r], k2);
                float s3 = SCORE(cf[r], k3);
                float p1 = p1f[r], p5 = p5f[r];
                c1t[r] += (s0 < p1) + (s1 < p1) + (s2 < p1) + (s3 < p1);
                int wx = (s0 >= p1) & (s0 < p5);
                int wy = (s1 >= p1) & (s1 < p5);
                int wz = (s2 >= p1) & (s2 < p5);
                int ww = (s3 >= p1) & (s3 < p5);
                int nc = wx + wy + wz + ww;
                if (nc) {
                    int g = rg * 4 + r;
                    unsigned bs = atomicAdd(&cnt[g], (unsigned)nc);
                    if (bs + (unsigned)nc <= CAPR) {
                        unsigned p = bs;
                        unsigned* rb = buf + g * CAPR;
                        if (wx) rb[p++] = ordkey(s0);
                        if (wy) rb[p++] = ordkey(s1);
                        if (wz) rb[p++] = ordkey(s2);
                        if (ww) rb[p++] = ordkey(s3);
                    }
                }
            }
        }
        #pragma unroll
        for (int r = 0; r < 4; r++) c1t[r] = __reduce_add_sync(0xffffffffu, c1t[r]);
        if (lane == 0) {
            #pragma unroll
            for (int r = 0; r < 4; r++) wred[wid*4 + r] = (unsigned)c1t[r];
        }
    }
    __syncthreads();

    // classify 8 rows (thread g handles global row g)
    if (tid < ROWS) {
        int g = tid, grp = g >> 2, rl = g & 3;
        int c1v = 0;
        for (int w = 0; w < 4; w++) c1v += (int)wred[(grp*4 + w)*4 + rl];
        int cw  = (int)cnt[g];
        int c5v = c1v + cw;
        unsigned p1 = spv1[g], p5 = spv5[g];
        if (c1v <= RANK && RANK < c5v && cw <= CAPR) {
            state[g] = 1u; slo[g] = p1; shi[g] = p5;
            stgt[g] = (unsigned)(RANK - c1v);
        } else {
            unsigned lo, hi; int clo, chi;
            if (RANK < c1v)      { lo = 0u; hi = p1; clo = 0;   chi = c1v; }
            else if (RANK < c5v) { lo = p1; hi = p5; clo = c1v; chi = c5v; }
            else                 { lo = p5; hi = ordkey(sMb[g]) + 1u; clo = c5v; chi = NTOK; }
            slo[g] = lo; shi[g] = hi; sclo[g] = clo; schi[g] = chi;
            if (hi - lo <= 1u)          { stkey[g] = lo; state[g] = 2u; }
            else if (chi - clo <= CAPR) { state[g] = 3u; }
            else { state[g] = 0u; spiv[g] = next_pivot(lo, hi, clo, chi, 1); }
        }
    }

    // fallback bisect loop (rare): each half recounts its 4 rows
    for (int iter = 0; iter < 72; iter++) {
        __syncthreads();
        if (tid == 0) {
            int a = 0;
            #pragma unroll
            for (int g = 0; g < ROWS; g++) a |= (state[g] == 0);
            sany[0] = a;
        }
        __syncthreads();
        if (!sany[0]) break;
        float pvf[4]; int act[4];
        #pragma unroll
        for (int r = 0; r < 4; r++) {
            int g = rg * 4 + r;
            act[r] = (state[g] == 0);
            pvf[r] = inv_ordkey(spiv[g]);
        }
        int cr[4] = {0,0,0,0};
        #pragma unroll 1
        for (int jo = 0; jo < 8; jo++) {
            int mb = (jo << 9) + (ht << 2);
            float4 k0 = __ldg(&kt[mb+0]);
            float4 k1 = __ldg(&kt[mb+1]);
            float4 k2 = __ldg(&kt[mb+2]);
            float4 k3 = __ldg(&kt[mb+3]);
            #pragma unroll
            for (int r = 0; r < 4; r++) {
                if (act[r]) {
                    float s0 = SCORE(cf[r], k0);
                    float s1 = SCORE(cf[r], k1);
                    float s2 = SCORE(cf[r], k2);
                    float s3 = SCORE(cf[r], k3);
                    cr[r] += (s0 < pvf[r]) + (s1 < pvf[r]) + (s2 < pvf[r]) + (s3 < pvf[r]);
                }
            }
        }
        #pragma unroll
        for (int r = 0; r < 4; r++) cr[r] = __reduce_add_sync(0xffffffffu, cr[r]);
        if (lane == 0) {
            #pragma unroll
            for (int r = 0; r < 4; r++) wred[wid*4 + r] = (unsigned)cr[r];
        }
        __syncthreads();
        if (tid < ROWS && state[tid] == 0) {
            int g = tid, grp = g >> 2, rl = g & 3;
            int tot = 0;
            for (int w = 0; w < 4; w++) tot += (int)wred[(grp*4 + w)*4 + rl];
            if (tot <= RANK) { slo[g] = spiv[g]; sclo[g] = tot; }
            else             { shi[g] = spiv[g]; schi[g] = tot; }
            unsigned lo = slo[g], hi = shi[g];
            int cc = schi[g] - sclo[g];
            if (hi - lo <= 1u)      { stkey[g] = lo; state[g] = 2; }
            else if (cc <= CAPR)    { state[g] = 3; }
            else spiv[g] = next_pivot(lo, hi, sclo[g], schi[g], !(iter & 1));
        }
    }
    __syncthreads();
    if (tid < ROWS) {
        if (state[tid] == 0) { stkey[tid] = slo[tid]; state[tid] = 2; } // safety
        if (state[tid] == 3) cnt[tid] = 0;
    }
    __syncthreads();

    // fallback compaction (rare): each half handles its rows
    {
        int anyc = 0;
        #pragma unroll
        for (int g = 0; g < ROWS; g++) anyc |= (state[g] == 3);
        if (anyc) {
            #pragma unroll 1
            for (int r = 0; r < 4; r++) {
                int g = rg * 4 + r;
                if (state[g] == 3) {
                    float lof = inv_ordkey(slo[g]);
                    float hif = inv_ordkey(shi[g]);
                    #pragma unroll 1
                    for (int jo = 0; jo < 8; jo++) {
                        int mb = (jo << 9) + (ht << 2);
                        float4 k0 = __ldg(&kt[mb+0]);
                        float4 k1 = __ldg(&kt[mb+1]);
                        float4 k2 = __ldg(&kt[mb+2]);
                        float4 k3 = __ldg(&kt[mb+3]);
                        float s0 = SCORE(cf[r], k0);
                        float s1 = SCORE(cf[r], k1);
                        float s2 = SCORE(cf[r], k2);
                        float s3 = SCORE(cf[r], k3);
                        int wx = (s0 >= lof) & (s0 < hif);
                        int wy = (s1 >= lof) & (s1 < hif);
                        int wz = (s2 >= lof) & (s2 < hif);
                        int ww = (s3 >= lof) & (s3 < hif);
                        int nc = wx + wy + wz + ww;
                        if (nc) {
                            unsigned bs = atomicAdd(&cnt[g], (unsigned)nc);
                            if (bs + (unsigned)nc <= CAPR) {
                                unsigned p = bs;
                                unsigned* rb = buf + g * CAPR;
                                if (wx) rb[p++] = ordkey(s0);
                                if (wy) rb[p++] = ordkey(s1);
                                if (wz) rb[p++] = ordkey(s2);
                                if (ww) rb[p++] = ordkey(s3);
                            }
                        }
                    }
                }
            }
            __syncthreads();
            if (tid < ROWS && state[tid] == 3) {
                stgt[tid] = (unsigned)(RANK - sclo[tid]);
                state[tid] = 1;
            }
            __syncthreads();
        }
    }

    // warp-register bisect (warp g handles global row g), write threshold
    {
        int g = wid;
        if (state[g] == 1) {
            int c = (int)cnt[g]; if (c > CAPR) c = CAPR;
            const unsigned* rb = buf + g * CAPR;
            unsigned cand[NREG];
            #pragma unroll
            for (int i = 0; i < NREG; i++) {
                int idx = i * 32 + lane;
                cand[i] = (idx < c) ? rb[idx] : 0xFFFFFFFFu;
            }
            unsigned lo = slo[g], hi = shi[g], tgt = stgt[g];
            while (hi - lo > 1u) {
                unsigned mid = lo + ((hi - lo) >> 1);
                unsigned cb = 0;
                #pragma unroll
                for (int i = 0; i < NREG; i++) cb += (cand[i] < mid);
                cb = __reduce_add_sync(0xffffffffu, cb);
                if (cb <= tgt) lo = mid; else hi = mid;
            }
            if (lane == 0) stkey[g] = lo;
        }
        __syncwarp();
        if (lane == 0) g_thr[head * NTOK + n0 + g] = inv_ordkey(stkey[g]);
    }
}

// ---------------- kernel 3b: masked softmax + p@v (8 rows/CTA, 4 per warp-half) ----------------
__global__ void __launch_bounds__(THREADS, 3) apply_kernel(const float* __restrict__ temperature) {
    __shared__ float sred[40 * 4];
    __shared__ float sfin[40];

    int bx   = blockIdx.x;
    int head = bx >> 9;
    int n0   = (bx & 511) << 3;
    int tid  = threadIdx.x;
    int lane = tid & 31, wid = tid >> 5;
    int rg   = wid >> 2;
    int ht   = tid & 127;
    int b0   = n0 + rg * 4;

    float temp = temperature[head];
    float4 cf[4];
    row_coeffs4(head, b0, temp, cf);
    float thrf[4];
    #pragma unroll
    for (int r = 0; r < 4; r++) thrf[r] = g_thr[head * NTOK + b0 + r];

    float zz[4] = {0.f, 0.f, 0.f, 0.f};
    float4 acc[4];
    #pragma unroll
    for (int r = 0; r < 4; r++) acc[r] = make_float4(0.f, 0.f, 0.f, 0.f);
    const float4* kt = g_kT + head * NTOK;
    const float4* vt = g_vT + head * NTOK;
    #pragma unroll
    for (int jo = 0; jo < 8; jo++) {
        #pragma unroll
        for (int hh = 0; hh < 2; hh++) {
            int m = (jo << 9) + (ht << 2) + hh * 2;
            float4 k0 = __ldg(&kt[m+0]);
            float4 k1 = __ldg(&kt[m+1]);
            float4 v0 = __ldg(&vt[m+0]);
            float4 v1 = __ldg(&vt[m+1]);
            #pragma unroll
            for (int r = 0; r < 4; r++) {
                float s0 = SCORE(cf[r], k0);
                float s1 = SCORE(cf[r], k1);
                float w0 = (s0 >= thrf[r]) ? __expf(s0) : 0.f;
                float w1 = (s1 >= thrf[r]) ? __expf(s1) : 0.f;
                zz[r] += w0 + w1;
                acc[r].x += w0*v0.x + w1*v1.x;
                acc[r].y += w0*v0.y + w1*v1.y;
                acc[r].z += w0*v0.z + w1*v1.z;
                acc[r].w += w0*v0.w + w1*v1.w;
            }
        }
    }

    // reduce: 20 values per half; global 40 slots, 4 warp-partials each
    float vals[20];
    #pragma unroll
    for (int r = 0; r < 4; r++) {
        vals[r*5 + 0] = zz[r];
        vals[r*5 + 1] = acc[r].x; vals[r*5 + 2] = acc[r].y;
        vals[r*5 + 3] = acc[r].z; vals[r*5 + 4] = acc[r].w;
    }
    #pragma unroll
    for (int q = 0; q < 20; q++)
        for (int off = 16; off; off >>= 1)
            vals[q] += __shfl_down_sync(0xffffffffu, vals[q], off);
    if (lane == 0) {
        #pragma unroll
        for (int q = 0; q < 20; q++)
            sred[(rg * 20 + q) * 4 + (wid & 3)] = vals[q];
    }
    __syncthreads();
    if (tid < 40) {
        float s = 0.f;
        for (int w = 0; w < 4; w++) s += sred[tid*4 + w];
        sfin[tid] = s;
    }
    __syncthreads();
    if (tid < 32) {
        int r = tid >> 2, c = tid & 3;   // global row r in 0..7
        float val = sfin[r*5 + 1 + c] / sfin[r*5 + 0];
        int n = n0 + r;
        int tt = n & 3, pixel = n >> 2;
        int ch = tt * 32 + head * 4 + c;
        g_pre[ch * 1024 + pixel] = val;
    }
}

// ---------------- kernel 4: final 1x1 projection ----------------
__global__ void proj_kernel(const float* __restrict__ wproj, float* __restrict__ out) {
    int idx = blockIdx.x * THREADS + threadIdx.x;
    int o = idx >> 10, p = idx & 1023;
    const float* w = wproj + o * 128;
    float s = 0.f;
    #pragma unroll 8
    for (int ch = 0; ch < 128; ch++) s += w[ch] * g_pre[ch * 1024 + p];
    out[idx] = s;
}

// ---------------- launch ----------------
extern "C" void kernel_launch(void* const* d_in, const int* in_sizes, int n_in,
                              void* d_out, int out_size) {
    (void)in_sizes; (void)n_in; (void)out_size;
    const float* x           = (const float*)d_in[0];
    const float* temperature = (const float*)d_in[1];
    const float* wqkv        = (const float*)d_in[2];
    const float* wdw         = (const float*)d_in[3];
    const float* wproj       = (const float*)d_in[4];
    float* out = (float*)d_out;

    prep_kernel<<<dim3(12, 32), THREADS>>>(x, wqkv, wdw);
    norm_kernel<<<72, THREADS>>>();
    select_kernel<<<HEADS * (NTOK / ROWS), THREADS>>>(temperature);
    apply_kernel<<<HEADS * (NTOK / ROWS), THREADS>>>(temperature);
    proj_kernel<<<(128 * 1024) / THREADS, THREADS>>>(wproj, out);
}